// round 1
// baseline (speedup 1.0000x reference)
#include <cuda_runtime.h>
#include <cuda_bf16.h>
#include <math.h>

// Problem constants
#define Bn 64
#define Sn 128
#define Hn 512
#define En 300
#define Vn 50257
#define H2n 1024          // 2H
#define H3n 1536          // 3H
#define XDIM 1324         // E + 2H  (GRU input)
#define CDIM 1836         // 3H + E  (output concat: h_new | weighted | embedded)
#define NEGV -1e10f

// d_out layout: prediction [B,V] | h_new [B,H] | a [B,S]
#define PRED_OFF 0
#define HN_OFF   ((size_t)Bn * Vn)
#define A_OFF    (HN_OFF + (size_t)Bn * Hn)

// ---------------- scratch (static device globals; no allocation) ----------------
__device__ float g_emb[Bn * En];
__device__ float g_hidpart[Bn * Hn];          // hidden @ W_attn[:, :H].T + b_attn
__device__ float g_energy[(size_t)Bn * Sn * Hn];  // pre-tanh energy, 16 MB
__device__ float g_scores[Bn * Sn];
__device__ float g_attn[Bn * Sn];
__device__ float g_weighted[Bn * H2n];
__device__ float g_gx[Bn * H3n];
__device__ float g_gh[Bn * H3n];
__device__ float g_xcat[Bn * CDIM];

// ---------------- 1) embedding gather ----------------
__global__ void k_emb(const int* __restrict__ ids, const float* __restrict__ table) {
    int idx = blockIdx.x * blockDim.x + threadIdx.x;
    if (idx >= Bn * En) return;
    int b = idx / En, e = idx - b * En;
    g_emb[idx] = table[(size_t)ids[b] * En + e];
}

// ---------------- 2) hid_part[b,h] = sum_k hidden[b,k] * W_attn[h,k] + b_attn[h] ----------------
__global__ void k_hidpart(const float* __restrict__ hidden, const float* __restrict__ Wa,
                          const float* __restrict__ ba) {
    int idx = blockIdx.x * blockDim.x + threadIdx.x;
    if (idx >= Bn * Hn) return;
    int b = idx / Hn, h = idx - b * Hn;
    const float* hr = hidden + (size_t)b * Hn;
    const float* wr = Wa + (size_t)h * H3n;
    float acc = ba[h];
    #pragma unroll 8
    for (int k = 0; k < Hn; k++) acc += hr[k] * wr[k];
    g_hidpart[idx] = acc;
}

// ---------------- 3) energy GEMM: E[b,s,h] = enc[s,b,:] dot W_attn[h, H: ] + hid_part[b,h] ----------------
// grid: (4 h-chunks, 64 b), 256 threads, tile M=128(s) N=128(h) K-step 32
__global__ __launch_bounds__(256, 2)
void k_energy(const float* __restrict__ enc, const float* __restrict__ Wa) {
    const int b  = blockIdx.y;
    const int h0 = blockIdx.x * 128;
    __shared__ float As[32][132];  // [k][s]
    __shared__ float Bs[32][132];  // [k][h]
    const int tid = threadIdx.x;
    const int tx = tid & 15, ty = tid >> 4;   // tx -> h, ty -> s
    float acc[8][8];
    #pragma unroll
    for (int i = 0; i < 8; i++)
        #pragma unroll
        for (int j = 0; j < 8; j++) acc[i][j] = 0.f;

    for (int k0 = 0; k0 < H2n; k0 += 32) {
        #pragma unroll
        for (int i = 0; i < 16; i++) {
            int idx = tid + i * 256;
            int s = idx >> 5, k = idx & 31;
            As[k][s] = enc[((size_t)(s * Bn + b)) * H2n + k0 + k];
        }
        #pragma unroll
        for (int i = 0; i < 16; i++) {
            int idx = tid + i * 256;
            int h = idx >> 5, k = idx & 31;
            Bs[k][h] = Wa[(size_t)(h0 + h) * H3n + Hn + k0 + k];
        }
        __syncthreads();
        #pragma unroll
        for (int kk = 0; kk < 32; kk++) {
            float a[8], w[8];
            #pragma unroll
            for (int i = 0; i < 8; i++) a[i] = As[kk][ty * 8 + i];
            #pragma unroll
            for (int j = 0; j < 8; j++) w[j] = Bs[kk][tx * 8 + j];
            #pragma unroll
            for (int i = 0; i < 8; i++)
                #pragma unroll
                for (int j = 0; j < 8; j++) acc[i][j] += a[i] * w[j];
        }
        __syncthreads();
    }
    #pragma unroll
    for (int i = 0; i < 8; i++) {
        int s = ty * 8 + i;
        #pragma unroll
        for (int j = 0; j < 8; j++) {
            int h = h0 + tx * 8 + j;
            g_energy[((size_t)(b * Sn + s)) * Hn + h] = acc[i][j] + g_hidpart[b * Hn + h];
        }
    }
}

// ---------------- 4) scores[b,s] = sum_h v[h]*tanh(E[b,s,h]); mask ----------------
__global__ void k_score(const float* __restrict__ vw, const int* __restrict__ mask) {
    int p = blockIdx.x;            // b*S+s
    int t = threadIdx.x;           // 128 threads
    const float* er = g_energy + (size_t)p * Hn;
    float sum = 0.f;
    #pragma unroll
    for (int i = t; i < Hn; i += 128) sum += vw[i] * tanhf(er[i]);
    __shared__ float red[128];
    red[t] = sum; __syncthreads();
    #pragma unroll
    for (int off = 64; off > 0; off >>= 1) {
        if (t < off) red[t] += red[t + off];
        __syncthreads();
    }
    if (t == 0) g_scores[p] = (mask[p] == 0) ? NEGV : red[0];
}

// ---------------- 5) softmax over S per b ----------------
__global__ void k_softmax(float* __restrict__ out_a) {
    int b = blockIdx.x, s = threadIdx.x;   // 128 threads
    float v = g_scores[b * Sn + s];
    __shared__ float red[128];
    red[s] = v; __syncthreads();
    #pragma unroll
    for (int off = 64; off > 0; off >>= 1) {
        if (s < off) red[s] = fmaxf(red[s], red[s + off]);
        __syncthreads();
    }
    float m = red[0]; __syncthreads();
    float e = expf(v - m);
    red[s] = e; __syncthreads();
    #pragma unroll
    for (int off = 64; off > 0; off >>= 1) {
        if (s < off) red[s] += red[s + off];
        __syncthreads();
    }
    float a = e / red[0];
    g_attn[b * Sn + s] = a;
    out_a[A_OFF + b * Sn + s] = a;
}

// ---------------- 6) weighted[b,e] = sum_s a[b,s]*enc[s,b,e] ----------------
__global__ void k_weighted(const float* __restrict__ enc) {
    int b = blockIdx.y;
    int e = blockIdx.x * 256 + threadIdx.x;
    __shared__ float as[Sn];
    if (threadIdx.x < Sn) as[threadIdx.x] = g_attn[b * Sn + threadIdx.x];
    __syncthreads();
    float acc = 0.f;
    #pragma unroll 4
    for (int s = 0; s < Sn; s++)
        acc += as[s] * enc[((size_t)(s * Bn + b)) * H2n + e];
    g_weighted[b * H2n + e] = acc;
}

// ---------------- 7) GRU matvecs: gx[b,j], gh[b,j] ----------------
__global__ void k_gxgh(const float* __restrict__ hidden,
                       const float* __restrict__ Wih, const float* __restrict__ Whh,
                       const float* __restrict__ bih, const float* __restrict__ bhh) {
    int idx = blockIdx.x * blockDim.x + threadIdx.x;   // j*64 + b : W rows broadcast in warp
    if (idx >= Bn * H3n) return;
    int j = idx >> 6, b = idx & 63;
    const float* wi = Wih + (size_t)j * XDIM;
    const float* eb = g_emb + b * En;
    const float* wt = g_weighted + b * H2n;
    float accx = bih[j];
    #pragma unroll 4
    for (int k = 0; k < En; k++) accx += eb[k] * wi[k];
    #pragma unroll 4
    for (int k = 0; k < H2n; k++) accx += wt[k] * wi[En + k];
    g_gx[b * H3n + j] = accx;

    const float* wh = Whh + (size_t)j * Hn;
    const float* hr = hidden + (size_t)b * Hn;
    float acch = bhh[j];
    #pragma unroll 4
    for (int k = 0; k < Hn; k++) acch += hr[k] * wh[k];
    g_gh[b * H3n + j] = acch;
}

// ---------------- 8) gates + h_new + build xcat ----------------
__global__ void k_gru_concat(const float* __restrict__ hidden, float* __restrict__ out) {
    int idx = blockIdx.x * blockDim.x + threadIdx.x;
    if (idx >= Bn * CDIM) return;
    int b = idx / CDIM, c = idx - b * CDIM;
    if (c < Hn) {
        float r = 1.f / (1.f + expf(-(g_gx[b * H3n + c] + g_gh[b * H3n + c])));
        float z = 1.f / (1.f + expf(-(g_gx[b * H3n + Hn + c] + g_gh[b * H3n + Hn + c])));
        float n = tanhf(g_gx[b * H3n + 2 * Hn + c] + r * g_gh[b * H3n + 2 * Hn + c]);
        float hn = (1.f - z) * n + z * hidden[(size_t)b * Hn + c];
        out[HN_OFF + b * Hn + c] = hn;
        g_xcat[idx] = hn;
    } else if (c < Hn + H2n) {
        g_xcat[idx] = g_weighted[b * H2n + (c - Hn)];
    } else {
        g_xcat[idx] = g_emb[b * En + (c - Hn - H2n)];
    }
}

// ---------------- 9) output GEMM: pred[b,v] = xcat[b,:] dot W_out[v,:] + b_out[v] ----------------
// grid: ceil(V/32), 256 threads; tile M=64(b) N=32(v) K-step 64
__global__ __launch_bounds__(256, 2)
void k_out(const float* __restrict__ Wout, const float* __restrict__ bout,
           float* __restrict__ pred) {
    const int v0 = blockIdx.x * 32;
    __shared__ float Xs[64][65];   // [k][b]
    __shared__ float Ws[64][33];   // [k][v]
    const int tid = threadIdx.x;
    const int tx = tid & 15, ty = tid >> 4;   // tx -> 4 b's, ty -> 2 v's
    float acc[4][2];
    #pragma unroll
    for (int i = 0; i < 4; i++) { acc[i][0] = 0.f; acc[i][1] = 0.f; }

    for (int k0 = 0; k0 < CDIM; k0 += 64) {
        #pragma unroll
        for (int i = 0; i < 16; i++) {
            int idx = tid + i * 256;
            int bb = idx >> 6, k = idx & 63;
            Xs[k][bb] = (k0 + k < CDIM) ? g_xcat[bb * CDIM + k0 + k] : 0.f;
        }
        #pragma unroll
        for (int i = 0; i < 8; i++) {
            int idx = tid + i * 256;
            int v = idx >> 6, k = idx & 63;
            float w = 0.f;
            if (v0 + v < Vn && k0 + k < CDIM)
                w = Wout[(size_t)(v0 + v) * CDIM + k0 + k];
            Ws[k][v] = w;
        }
        __syncthreads();
        #pragma unroll
        for (int kk = 0; kk < 64; kk++) {
            float x4[4], w2[2];
            #pragma unroll
            for (int i = 0; i < 4; i++) x4[i] = Xs[kk][tx * 4 + i];
            w2[0] = Ws[kk][ty * 2];
            w2[1] = Ws[kk][ty * 2 + 1];
            #pragma unroll
            for (int i = 0; i < 4; i++) {
                acc[i][0] += x4[i] * w2[0];
                acc[i][1] += x4[i] * w2[1];
            }
        }
        __syncthreads();
    }
    #pragma unroll
    for (int j = 0; j < 2; j++) {
        int v = v0 + ty * 2 + j;
        if (v < Vn) {
            float bo = bout[v];
            #pragma unroll
            for (int i = 0; i < 4; i++) {
                int b = tx * 4 + i;
                pred[(size_t)b * Vn + v] = acc[i][j] + bo;
            }
        }
    }
}

// ---------------- launch ----------------
extern "C" void kernel_launch(void* const* d_in, const int* in_sizes, int n_in,
                              void* d_out, int out_size) {
    const int*   ids    = (const int*)  d_in[0];
    const float* hidden = (const float*)d_in[1];
    const float* enc    = (const float*)d_in[2];
    const int*   mask   = (const int*)  d_in[3];
    const float* table  = (const float*)d_in[4];
    const float* Wa     = (const float*)d_in[5];
    const float* ba     = (const float*)d_in[6];
    const float* vw     = (const float*)d_in[7];
    const float* Wih    = (const float*)d_in[8];
    const float* Whh    = (const float*)d_in[9];
    const float* bih    = (const float*)d_in[10];
    const float* bhh    = (const float*)d_in[11];
    const float* Wout   = (const float*)d_in[12];
    const float* bout   = (const float*)d_in[13];
    float* out = (float*)d_out;

    k_emb<<<(Bn * En + 255) / 256, 256>>>(ids, table);
    k_hidpart<<<(Bn * Hn + 255) / 256, 256>>>(hidden, Wa, ba);
    k_energy<<<dim3(4, Bn), 256>>>(enc, Wa);
    k_score<<<Bn * Sn, 128>>>(vw, mask);
    k_softmax<<<Bn, Sn>>>(out);
    k_weighted<<<dim3(H2n / 256, Bn), 256>>>(enc);
    k_gxgh<<<(Bn * H3n + 255) / 256, 256>>>(hidden, Wih, Whh, bih, bhh);
    k_gru_concat<<<(Bn * CDIM + 255) / 256, 256>>>(hidden, out);
    k_out<<<(Vn + 31) / 32, 256>>>(Wout, bout, out + PRED_OFF);
}

// round 2
// speedup vs baseline: 1.5661x; 1.5661x over previous
#include <cuda_runtime.h>
#include <cuda_bf16.h>
#include <math.h>

#define Bn 64
#define Sn 128
#define Hn 512
#define En 300
#define Vn 50257
#define H2n 1024
#define H3n 1536
#define XDIM 1324         // E + 2H
#define CDIM 1836         // 3H + E
#define NEGV -1e10f

#define PRED_OFF 0
#define HN_OFF   ((size_t)Bn * Vn)
#define A_OFF    (HN_OFF + (size_t)Bn * Hn)

// ---------------- scratch ----------------
__device__ float g_emb[Bn * En];
__device__ float g_hidpart[Bn * Hn];
__device__ float g_scorep[Bn * 4 * Sn];   // per-h-chunk score partials
__device__ float g_attn[Bn * Sn];
__device__ float g_weighted[Bn * H2n];
__device__ float g_xin[Bn * XDIM];        // [emb | weighted]
__device__ float g_gx[Bn * H3n];
__device__ float g_gh[Bn * H3n];
__device__ float g_xcat[Bn * CDIM];

// ---------------- packed f32x2 helpers ----------------
__device__ __forceinline__ unsigned long long pk2(float lo, float hi) {
    unsigned long long r;
    asm("mov.b64 %0, {%1, %2};" : "=l"(r) : "f"(lo), "f"(hi));
    return r;
}
__device__ __forceinline__ void upk2(float& lo, float& hi, unsigned long long v) {
    asm("mov.b64 {%0, %1}, %2;" : "=f"(lo), "=f"(hi) : "l"(v));
}
#define FMA2(d, a, b) asm("fma.rn.f32x2 %0, %1, %2, %0;" : "+l"(d) : "l"(a), "l"(b))

// ---------------- 1) embedding gather ----------------
__global__ void k_emb(const int* __restrict__ ids, const float* __restrict__ table) {
    int idx = blockIdx.x * blockDim.x + threadIdx.x;
    if (idx >= Bn * En) return;
    int b = idx / En, e = idx - b * En;
    g_emb[idx] = table[(size_t)ids[b] * En + e];
}

// ---------------- generic small GEMM: out[b, j0+j] = A[b,:] . W[j,:] + bias[j] ----------------
// M=64 (all b), Ntile=128, Ktile=32. grid.x = N/128, 256 threads.
__global__ __launch_bounds__(256)
void k_gemm_small(const float* __restrict__ A, int astride, int K,
                  const float* __restrict__ W, int wstride,
                  const float* __restrict__ bias,
                  float* __restrict__ out, int ostride) {
    const int j0 = blockIdx.x * 128;
    __shared__ __align__(16) float As[32][68];   // [k][b]
    __shared__ __align__(16) float Ws[32][132];  // [k][j]
    const int tid = threadIdx.x;
    const int tx = tid & 15;   // j group: 8 each
    const int ty = tid >> 4;   // b group: 4 each
    float acc[4][8];
    #pragma unroll
    for (int i = 0; i < 4; i++)
        #pragma unroll
        for (int j = 0; j < 8; j++) acc[i][j] = 0.f;

    for (int k0 = 0; k0 < K; k0 += 32) {
        #pragma unroll
        for (int it = 0; it < 8; it++) {
            int idx = tid + it * 256;
            int b = idx >> 5, k = idx & 31;
            As[k][b] = (k0 + k < K) ? A[(size_t)b * astride + k0 + k] : 0.f;
        }
        #pragma unroll
        for (int it = 0; it < 16; it++) {
            int idx = tid + it * 256;
            int j = idx >> 5, k = idx & 31;
            Ws[k][j] = (k0 + k < K) ? W[(size_t)(j0 + j) * wstride + k0 + k] : 0.f;
        }
        __syncthreads();
        #pragma unroll
        for (int kk = 0; kk < 32; kk++) {
            float a[4], w[8];
            #pragma unroll
            for (int i = 0; i < 4; i++) a[i] = As[kk][ty * 4 + i];
            #pragma unroll
            for (int j = 0; j < 8; j++) w[j] = Ws[kk][tx * 8 + j];
            #pragma unroll
            for (int i = 0; i < 4; i++)
                #pragma unroll
                for (int j = 0; j < 8; j++) acc[i][j] += a[i] * w[j];
        }
        __syncthreads();
    }
    #pragma unroll
    for (int i = 0; i < 4; i++) {
        int b = ty * 4 + i;
        #pragma unroll
        for (int j = 0; j < 8; j++) {
            int jj = j0 + tx * 8 + j;
            out[(size_t)b * ostride + jj] = acc[i][j] + bias[jj];
        }
    }
}

// ---------------- 3) energy GEMM + fused v*tanh score partials ----------------
// grid: (4 h-chunks, 64 b), 256 threads, tile S=128 x H=128, Kstep 32, FFMA2.
__global__ __launch_bounds__(256, 2)
void k_energy(const float* __restrict__ enc, const float* __restrict__ Wa,
              const float* __restrict__ vw) {
    const int b  = blockIdx.y;
    const int h0 = blockIdx.x * 128;
    __shared__ __align__(16) float As[32][132];  // [k][s]
    __shared__ __align__(16) float Bs[32][132];  // [k][h]
    __shared__ float red[128][17];
    const int tid = threadIdx.x;
    const int tx = tid & 15;   // h: 8 each (4 f32x2 pairs)
    const int ty = tid >> 4;   // s: 8 each
    unsigned long long acc2[8][4];
    #pragma unroll
    for (int i = 0; i < 8; i++)
        #pragma unroll
        for (int j = 0; j < 4; j++) acc2[i][j] = 0ULL;

    for (int k0 = 0; k0 < H2n; k0 += 32) {
        #pragma unroll
        for (int it = 0; it < 16; it++) {
            int idx = tid + it * 256;
            int s = idx >> 5, k = idx & 31;
            As[k][s] = enc[((size_t)(s * Bn + b)) * H2n + k0 + k];
        }
        #pragma unroll
        for (int it = 0; it < 16; it++) {
            int idx = tid + it * 256;
            int h = idx >> 5, k = idx & 31;
            Bs[k][h] = Wa[(size_t)(h0 + h) * H3n + Hn + k0 + k];
        }
        __syncthreads();
        #pragma unroll
        for (int kk = 0; kk < 32; kk++) {
            const float4* ap = (const float4*)&As[kk][ty * 8];
            float4 a0 = ap[0], a1 = ap[1];
            unsigned long long wq[4];
            #pragma unroll
            for (int j = 0; j < 4; j++)
                wq[j] = *(const unsigned long long*)&Bs[kk][tx * 8 + 2 * j];
            float av[8] = {a0.x, a0.y, a0.z, a0.w, a1.x, a1.y, a1.z, a1.w};
            #pragma unroll
            for (int i = 0; i < 8; i++) {
                unsigned long long ad = pk2(av[i], av[i]);
                #pragma unroll
                for (int j = 0; j < 4; j++) FMA2(acc2[i][j], ad, wq[j]);
            }
        }
        __syncthreads();
    }

    // epilogue: score partial p[s] = sum_h vw[h] * tanh(energy)
    float hp[8], vv[8];
    #pragma unroll
    for (int j = 0; j < 8; j++) {
        int h = h0 + tx * 8 + j;
        hp[j] = g_hidpart[b * Hn + h];
        vv[j] = vw[h];
    }
    #pragma unroll
    for (int i = 0; i < 8; i++) {
        float p = 0.f;
        #pragma unroll
        for (int j = 0; j < 4; j++) {
            float lo, hi;
            upk2(lo, hi, acc2[i][j]);
            p += vv[2 * j]     * tanhf(lo + hp[2 * j]);
            p += vv[2 * j + 1] * tanhf(hi + hp[2 * j + 1]);
        }
        red[ty * 8 + i][tx] = p;
    }
    __syncthreads();
    if (tid < 128) {
        float s = 0.f;
        #pragma unroll
        for (int t = 0; t < 16; t++) s += red[tid][t];
        g_scorep[(b * 4 + blockIdx.x) * Sn + tid] = s;
    }
}

// ---------------- 4) score assemble + mask + softmax ----------------
__global__ void k_softmax(const int* __restrict__ mask, float* __restrict__ out_a) {
    int b = blockIdx.x, s = threadIdx.x;   // 128 threads
    float v = 0.f;
    #pragma unroll
    for (int c = 0; c < 4; c++) v += g_scorep[(b * 4 + c) * Sn + s];
    if (mask[b * Sn + s] == 0) v = NEGV;
    __shared__ float red[128];
    red[s] = v; __syncthreads();
    #pragma unroll
    for (int off = 64; off > 0; off >>= 1) {
        if (s < off) red[s] = fmaxf(red[s], red[s + off]);
        __syncthreads();
    }
    float m = red[0]; __syncthreads();
    float e = expf(v - m);
    red[s] = e; __syncthreads();
    #pragma unroll
    for (int off = 64; off > 0; off >>= 1) {
        if (s < off) red[s] += red[s + off];
        __syncthreads();
    }
    float a = e / red[0];
    g_attn[b * Sn + s] = a;
    out_a[A_OFF + b * Sn + s] = a;
}

// ---------------- 5) weighted[b,e] = sum_s a[b,s]*enc[s,b,e] ----------------
__global__ void k_weighted(const float* __restrict__ enc) {
    int b = blockIdx.y;
    int e = blockIdx.x * 256 + threadIdx.x;
    __shared__ float as[Sn];
    if (threadIdx.x < Sn) as[threadIdx.x] = g_attn[b * Sn + threadIdx.x];
    __syncthreads();
    float acc = 0.f;
    #pragma unroll 4
    for (int s = 0; s < Sn; s++)
        acc += as[s] * enc[((size_t)(s * Bn + b)) * H2n + e];
    g_weighted[b * H2n + e] = acc;
}

// ---------------- 6) build x = [emb | weighted] ----------------
__global__ void k_xin() {
    int idx = blockIdx.x * blockDim.x + threadIdx.x;
    if (idx >= Bn * XDIM) return;
    int b = idx / XDIM, c = idx - b * XDIM;
    g_xin[idx] = (c < En) ? g_emb[b * En + c] : g_weighted[b * H2n + (c - En)];
}

// ---------------- 7) gates + h_new + build xcat ----------------
__global__ void k_gru_concat(const float* __restrict__ hidden, float* __restrict__ out) {
    int idx = blockIdx.x * blockDim.x + threadIdx.x;
    if (idx >= Bn * CDIM) return;
    int b = idx / CDIM, c = idx - b * CDIM;
    if (c < Hn) {
        float r = 1.f / (1.f + expf(-(g_gx[b * H3n + c] + g_gh[b * H3n + c])));
        float z = 1.f / (1.f + expf(-(g_gx[b * H3n + Hn + c] + g_gh[b * H3n + Hn + c])));
        float n = tanhf(g_gx[b * H3n + 2 * Hn + c] + r * g_gh[b * H3n + 2 * Hn + c]);
        float hn = (1.f - z) * n + z * hidden[(size_t)b * Hn + c];
        out[HN_OFF + b * Hn + c] = hn;
        g_xcat[idx] = hn;
    } else if (c < Hn + H2n) {
        g_xcat[idx] = g_weighted[b * H2n + (c - Hn)];
    } else {
        g_xcat[idx] = g_emb[b * En + (c - Hn - H2n)];
    }
}

// ---------------- 8) output GEMM (FFMA2): pred[b,v] = xcat[b,:].Wout[v,:] + bout[v] ----------------
// tile M=64(b) x N=128(v), Kstep 64, 256 threads, grid ceil(V/128)
__global__ __launch_bounds__(256)
void k_out(const float* __restrict__ Wout, const float* __restrict__ bout,
           float* __restrict__ pred) {
    const int v0 = blockIdx.x * 128;
    __shared__ __align__(16) float Xs[64][68];   // [k][b]
    __shared__ __align__(16) float Ws[64][132];  // [k][v]
    const int tid = threadIdx.x;
    const int tx = tid & 15;   // v: 8 each (4 pairs)
    const int ty = tid >> 4;   // b: 4 each
    unsigned long long acc2[4][4];
    #pragma unroll
    for (int i = 0; i < 4; i++)
        #pragma unroll
        for (int j = 0; j < 4; j++) acc2[i][j] = 0ULL;

    for (int k0 = 0; k0 < CDIM; k0 += 64) {
        #pragma unroll
        for (int it = 0; it < 16; it++) {
            int idx = tid + it * 256;
            int bb = idx >> 6, k = idx & 63;
            Xs[k][bb] = (k0 + k < CDIM) ? g_xcat[bb * CDIM + k0 + k] : 0.f;
        }
        #pragma unroll
        for (int it = 0; it < 32; it++) {
            int idx = tid + it * 256;
            int v = idx >> 6, k = idx & 63;
            float w = 0.f;
            if (v0 + v < Vn && k0 + k < CDIM)
                w = Wout[(size_t)(v0 + v) * CDIM + k0 + k];
            Ws[k][v] = w;
        }
        __syncthreads();
        #pragma unroll
        for (int kk = 0; kk < 64; kk++) {
            float4 x = *(const float4*)&Xs[kk][ty * 4];
            unsigned long long wq[4];
            #pragma unroll
            for (int j = 0; j < 4; j++)
                wq[j] = *(const unsigned long long*)&Ws[kk][tx * 8 + 2 * j];
            float xv[4] = {x.x, x.y, x.z, x.w};
            #pragma unroll
            for (int i = 0; i < 4; i++) {
                unsigned long long xd = pk2(xv[i], xv[i]);
                #pragma unroll
                for (int j = 0; j < 4; j++) FMA2(acc2[i][j], xd, wq[j]);
            }
        }
        __syncthreads();
    }
    #pragma unroll
    for (int i = 0; i < 4; i++) {
        int b = ty * 4 + i;
        #pragma unroll
        for (int j = 0; j < 4; j++) {
            int v = v0 + tx * 8 + 2 * j;
            float lo, hi;
            upk2(lo, hi, acc2[i][j]);
            if (v < Vn)     pred[(size_t)b * Vn + v]     = lo + bout[v];
            if (v + 1 < Vn) pred[(size_t)b * Vn + v + 1] = hi + bout[v + 1];
        }
    }
}

// ---------------- launch ----------------
extern "C" void kernel_launch(void* const* d_in, const int* in_sizes, int n_in,
                              void* d_out, int out_size) {
    const int*   ids    = (const int*)  d_in[0];
    const float* hidden = (const float*)d_in[1];
    const float* enc    = (const float*)d_in[2];
    const int*   mask   = (const int*)  d_in[3];
    const float* table  = (const float*)d_in[4];
    const float* Wa     = (const float*)d_in[5];
    const float* ba     = (const float*)d_in[6];
    const float* vw     = (const float*)d_in[7];
    const float* Wih    = (const float*)d_in[8];
    const float* Whh    = (const float*)d_in[9];
    const float* bih    = (const float*)d_in[10];
    const float* bhh    = (const float*)d_in[11];
    const float* Wout   = (const float*)d_in[12];
    const float* bout   = (const float*)d_in[13];
    float* out = (float*)d_out;

    float* d_hidpart; cudaGetSymbolAddress((void**)&d_hidpart, g_hidpart);
    float* d_xin;     cudaGetSymbolAddress((void**)&d_xin,     g_xin);
    float* d_gx;      cudaGetSymbolAddress((void**)&d_gx,      g_gx);
    float* d_gh;      cudaGetSymbolAddress((void**)&d_gh,      g_gh);

    k_emb<<<(Bn * En + 255) / 256, 256>>>(ids, table);
    // hid_part = hidden @ Wa[:, :H].T + ba
    k_gemm_small<<<Hn / 128, 256>>>(hidden, Hn, Hn, Wa, H3n, ba, d_hidpart, Hn);
    k_energy<<<dim3(4, Bn), 256>>>(enc, Wa, vw);
    k_softmax<<<Bn, Sn>>>(mask, out);
    k_weighted<<<dim3(H2n / 256, Bn), 256>>>(enc);
    k_xin<<<(Bn * XDIM + 255) / 256, 256>>>();
    // gx = xin @ Wih.T + bih ; gh = hidden @ Whh.T + bhh
    k_gemm_small<<<H3n / 128, 256>>>(d_xin, XDIM, XDIM, Wih, XDIM, bih, d_gx, H3n);
    k_gemm_small<<<H3n / 128, 256>>>(hidden, Hn, Hn, Whh, Hn, bhh, d_gh, H3n);
    k_gru_concat<<<(Bn * CDIM + 255) / 256, 256>>>(hidden, out);
    k_out<<<(Vn + 127) / 128, 256>>>(Wout, bout, out + PRED_OFF);
}

// round 4
// speedup vs baseline: 2.3822x; 1.5212x over previous
#include <cuda_runtime.h>
#include <cuda_bf16.h>
#include <math.h>
#include <stdint.h>

#define Bn 64
#define Sn 128
#define Hn 512
#define En 300
#define Vn 50257
#define H2n 1024
#define H3n 1536
#define XDIM 1324         // E + 2H
#define CDIM 1836         // 3H + E
#define NEGV -1e10f

#define PRED_OFF 0
#define HN_OFF   ((size_t)Bn * Vn)
#define A_OFF    (HN_OFF + (size_t)Bn * Hn)

// ---------------- scratch ----------------
__device__ float g_emb[Bn * En];
__device__ float g_hidpart[Bn * Hn];
__device__ float g_scorep[Bn * 4 * Sn];
__device__ float g_attn[Bn * Sn];
__device__ float g_weighted[Bn * H2n];
__device__ float g_xin[Bn * XDIM];
__device__ float g_gx[Bn * H3n];
__device__ float g_gh[Bn * H3n];
__device__ float g_xcat[Bn * CDIM];

// ---------------- packed f32x2 helpers (FFMA2) ----------------
__device__ __forceinline__ unsigned long long pk2(float lo, float hi) {
    unsigned long long r;
    asm("mov.b64 %0, {%1, %2};" : "=l"(r) : "f"(lo), "f"(hi));
    return r;
}
__device__ __forceinline__ void upk2(float& lo, float& hi, unsigned long long v) {
    asm("mov.b64 {%0, %1}, %2;" : "=f"(lo), "=f"(hi) : "l"(v));
}
#define FMA2(d, a, b) asm("fma.rn.f32x2 %0, %1, %2, %0;" : "+l"(d) : "l"(a), "l"(b))

// ---------------- mma.sync helpers (bf16, sm_80+ path; works on sm_103 base) ----------------
__device__ __forceinline__ uint32_t smem_u32(const void* p) {
    uint32_t a;
    asm("{ .reg .u64 t; cvta.to.shared.u64 t, %1; cvt.u32.u64 %0, t; }" : "=r"(a) : "l"(p));
    return a;
}
__device__ __forceinline__ void ldmx4(uint32_t* r, uint32_t addr) {
    asm volatile("ldmatrix.sync.aligned.m8n8.x4.shared.b16 {%0,%1,%2,%3}, [%4];"
                 : "=r"(r[0]), "=r"(r[1]), "=r"(r[2]), "=r"(r[3]) : "r"(addr));
}
__device__ __forceinline__ void mma16816(float* c, const uint32_t* a, const uint32_t* b) {
    asm volatile("mma.sync.aligned.m16n8k16.row.col.f32.bf16.bf16.f32 "
                 "{%0,%1,%2,%3}, {%4,%5,%6,%7}, {%8,%9}, {%0,%1,%2,%3};"
                 : "+f"(c[0]), "+f"(c[1]), "+f"(c[2]), "+f"(c[3])
                 : "r"(a[0]), "r"(a[1]), "r"(a[2]), "r"(a[3]), "r"(b[0]), "r"(b[1]));
}
// truncation hi/lo split of two floats -> packed bf16x2 words (lo exact residual, rn)
__device__ __forceinline__ void split2t(float x, float y, uint32_t& hiw, uint32_t& low) {
    uint32_t xb = __float_as_uint(x), yb = __float_as_uint(y);
    uint32_t hx = xb & 0xFFFF0000u, hy = yb & 0xFFFF0000u;
    hiw = (hx >> 16) | hy;
    float lx = x - __uint_as_float(hx);
    float ly = y - __uint_as_float(hy);
    asm("cvt.rn.bf16x2.f32 %0, %1, %2;" : "=r"(low) : "f"(ly), "f"(lx));
}

// ---------------- 1) embedding gather ----------------
__global__ void k_emb(const int* __restrict__ ids, const float* __restrict__ table) {
    int idx = blockIdx.x * blockDim.x + threadIdx.x;
    if (idx >= Bn * En) return;
    int b = idx / En, e = idx - b * En;
    g_emb[idx] = table[(size_t)ids[b] * En + e];
}

// ---------------- small GEMM (fp32) ----------------
__global__ __launch_bounds__(256)
void k_gemm_small(const float* __restrict__ A, int astride, int K,
                  const float* __restrict__ W, int wstride,
                  const float* __restrict__ bias,
                  float* __restrict__ out, int ostride) {
    const int j0 = blockIdx.x * 128;
    __shared__ __align__(16) float As[32][68];
    __shared__ __align__(16) float Ws[32][132];
    const int tid = threadIdx.x;
    const int tx = tid & 15, ty = tid >> 4;
    float acc[4][8];
    #pragma unroll
    for (int i = 0; i < 4; i++)
        #pragma unroll
        for (int j = 0; j < 8; j++) acc[i][j] = 0.f;

    for (int k0 = 0; k0 < K; k0 += 32) {
        #pragma unroll
        for (int it = 0; it < 8; it++) {
            int idx = tid + it * 256;
            int b = idx >> 5, k = idx & 31;
            As[k][b] = (k0 + k < K) ? A[(size_t)b * astride + k0 + k] : 0.f;
        }
        #pragma unroll
        for (int it = 0; it < 16; it++) {
            int idx = tid + it * 256;
            int j = idx >> 5, k = idx & 31;
            Ws[k][j] = (k0 + k < K) ? W[(size_t)(j0 + j) * wstride + k0 + k] : 0.f;
        }
        __syncthreads();
        #pragma unroll
        for (int kk = 0; kk < 32; kk++) {
            float a[4], w[8];
            #pragma unroll
            for (int i = 0; i < 4; i++) a[i] = As[kk][ty * 4 + i];
            #pragma unroll
            for (int j = 0; j < 8; j++) w[j] = Ws[kk][tx * 8 + j];
            #pragma unroll
            for (int i = 0; i < 4; i++)
                #pragma unroll
                for (int j = 0; j < 8; j++) acc[i][j] += a[i] * w[j];
        }
        __syncthreads();
    }
    #pragma unroll
    for (int i = 0; i < 4; i++) {
        int b = ty * 4 + i;
        #pragma unroll
        for (int j = 0; j < 8; j++) {
            int jj = j0 + tx * 8 + j;
            out[(size_t)b * ostride + jj] = acc[i][j] + bias[jj];
        }
    }
}

// ---------------- 3) energy GEMM (FFMA2) + fused v*tanh score partials ----------------
__global__ __launch_bounds__(256, 2)
void k_energy(const float* __restrict__ enc, const float* __restrict__ Wa,
              const float* __restrict__ vw) {
    const int b  = blockIdx.y;
    const int h0 = blockIdx.x * 128;
    __shared__ __align__(16) float As[32][132];
    __shared__ __align__(16) float Bs[32][132];
    __shared__ float red[128][17];
    const int tid = threadIdx.x;
    const int tx = tid & 15, ty = tid >> 4;
    unsigned long long acc2[8][4];
    #pragma unroll
    for (int i = 0; i < 8; i++)
        #pragma unroll
        for (int j = 0; j < 4; j++) acc2[i][j] = 0ULL;

    for (int k0 = 0; k0 < H2n; k0 += 32) {
        #pragma unroll
        for (int it = 0; it < 16; it++) {
            int idx = tid + it * 256;
            int s = idx >> 5, k = idx & 31;
            As[k][s] = enc[((size_t)(s * Bn + b)) * H2n + k0 + k];
        }
        #pragma unroll
        for (int it = 0; it < 16; it++) {
            int idx = tid + it * 256;
            int h = idx >> 5, k = idx & 31;
            Bs[k][h] = Wa[(size_t)(h0 + h) * H3n + Hn + k0 + k];
        }
        __syncthreads();
        #pragma unroll
        for (int kk = 0; kk < 32; kk++) {
            const float4* ap = (const float4*)&As[kk][ty * 8];
            float4 a0 = ap[0], a1 = ap[1];
            unsigned long long wq[4];
            #pragma unroll
            for (int j = 0; j < 4; j++)
                wq[j] = *(const unsigned long long*)&Bs[kk][tx * 8 + 2 * j];
            float av[8] = {a0.x, a0.y, a0.z, a0.w, a1.x, a1.y, a1.z, a1.w};
            #pragma unroll
            for (int i = 0; i < 8; i++) {
                unsigned long long ad = pk2(av[i], av[i]);
                #pragma unroll
                for (int j = 0; j < 4; j++) FMA2(acc2[i][j], ad, wq[j]);
            }
        }
        __syncthreads();
    }

    float hp[8], vv[8];
    #pragma unroll
    for (int j = 0; j < 8; j++) {
        int h = h0 + tx * 8 + j;
        hp[j] = g_hidpart[b * Hn + h];
        vv[j] = vw[h];
    }
    #pragma unroll
    for (int i = 0; i < 8; i++) {
        float p = 0.f;
        #pragma unroll
        for (int j = 0; j < 4; j++) {
            float lo, hi;
            upk2(lo, hi, acc2[i][j]);
            p += vv[2 * j]     * tanhf(lo + hp[2 * j]);
            p += vv[2 * j + 1] * tanhf(hi + hp[2 * j + 1]);
        }
        red[ty * 8 + i][tx] = p;
    }
    __syncthreads();
    if (tid < 128) {
        float s = 0.f;
        #pragma unroll
        for (int t = 0; t < 16; t++) s += red[tid][t];
        g_scorep[(b * 4 + blockIdx.x) * Sn + tid] = s;
    }
}

// ---------------- 4) softmax ----------------
__global__ void k_softmax(const int* __restrict__ mask, float* __restrict__ out_a) {
    int b = blockIdx.x, s = threadIdx.x;
    float v = 0.f;
    #pragma unroll
    for (int c = 0; c < 4; c++) v += g_scorep[(b * 4 + c) * Sn + s];
    if (mask[b * Sn + s] == 0) v = NEGV;
    __shared__ float red[128];
    red[s] = v; __syncthreads();
    #pragma unroll
    for (int off = 64; off > 0; off >>= 1) {
        if (s < off) red[s] = fmaxf(red[s], red[s + off]);
        __syncthreads();
    }
    float m = red[0]; __syncthreads();
    float e = expf(v - m);
    red[s] = e; __syncthreads();
    #pragma unroll
    for (int off = 64; off > 0; off >>= 1) {
        if (s < off) red[s] += red[s + off];
        __syncthreads();
    }
    float a = e / red[0];
    g_attn[b * Sn + s] = a;
    out_a[A_OFF + b * Sn + s] = a;
}

// ---------------- 5) weighted ----------------
__global__ void k_weighted(const float* __restrict__ enc) {
    int b = blockIdx.y;
    int e = blockIdx.x * 256 + threadIdx.x;
    __shared__ float as[Sn];
    if (threadIdx.x < Sn) as[threadIdx.x] = g_attn[b * Sn + threadIdx.x];
    __syncthreads();
    float acc = 0.f;
    #pragma unroll 4
    for (int s = 0; s < Sn; s++)
        acc += as[s] * enc[((size_t)(s * Bn + b)) * H2n + e];
    g_weighted[b * H2n + e] = acc;
}

// ---------------- 6) x = [emb | weighted] ----------------
__global__ void k_xin() {
    int idx = blockIdx.x * blockDim.x + threadIdx.x;
    if (idx >= Bn * XDIM) return;
    int b = idx / XDIM, c = idx - b * XDIM;
    g_xin[idx] = (c < En) ? g_emb[b * En + c] : g_weighted[b * H2n + (c - En)];
}

// ---------------- 7) gates + h_new + xcat ----------------
__global__ void k_gru_concat(const float* __restrict__ hidden, float* __restrict__ out) {
    int idx = blockIdx.x * blockDim.x + threadIdx.x;
    if (idx >= Bn * CDIM) return;
    int b = idx / CDIM, c = idx - b * CDIM;
    if (c < Hn) {
        float r = 1.f / (1.f + expf(-(g_gx[b * H3n + c] + g_gh[b * H3n + c])));
        float z = 1.f / (1.f + expf(-(g_gx[b * H3n + Hn + c] + g_gh[b * H3n + Hn + c])));
        float n = tanhf(g_gx[b * H3n + 2 * Hn + c] + r * g_gh[b * H3n + 2 * Hn + c]);
        float hn = (1.f - z) * n + z * hidden[(size_t)b * Hn + c];
        out[HN_OFF + b * Hn + c] = hn;
        g_xcat[idx] = hn;
    } else if (c < Hn + H2n) {
        g_xcat[idx] = g_weighted[b * H2n + (c - Hn)];
    } else {
        g_xcat[idx] = g_emb[b * En + (c - Hn - H2n)];
    }
}

// ---------------- 8) output GEMM via mma.sync bf16x3 ----------------
// Block: M=128(v) x N=64(b); 8 warps as 4(m) x 2(n); warp tile 32x32.
// K chunks of 32. Smem rows padded to 40 bf16 (80B) for conflict-free ldmatrix.
#define KC 32
#define WSTR 40           // bf16 elements per smem row
#define NCHUNK ((CDIM + KC - 1) / KC)   // 58

__global__ __launch_bounds__(256)
void k_out_mma(const float* __restrict__ Wout, const float* __restrict__ bout,
               float* __restrict__ pred) {
    __shared__ __align__(16) __nv_bfloat16 sWhi[128 * WSTR];
    __shared__ __align__(16) __nv_bfloat16 sWlo[128 * WSTR];
    __shared__ __align__(16) __nv_bfloat16 sXhi[64 * WSTR];
    __shared__ __align__(16) __nv_bfloat16 sXlo[64 * WSTR];

    const int tid = threadIdx.x;
    const int lane = tid & 31, wid = tid >> 5;
    const int wm = wid >> 1, wn = wid & 1;
    const int v0 = blockIdx.x * 128;

    const uint32_t bWhi = smem_u32(sWhi), bWlo = smem_u32(sWlo);
    const uint32_t bXhi = smem_u32(sXhi), bXlo = smem_u32(sXlo);

    float acc[2][4][4];
    #pragma unroll
    for (int i = 0; i < 2; i++)
        #pragma unroll
        for (int j = 0; j < 4; j++)
            #pragma unroll
            for (int q = 0; q < 4; q++) acc[i][j][q] = 0.f;

    // ldmatrix address components (constant across chunks)
    const int a_row = (lane & 15);            // + wm*32 + i*16
    const int a_col8 = (lane >> 4) * 8;       // + s*16
    const int g = lane >> 3;
    const int b_row = ((g >> 1) * 8) + (lane & 7);   // + wn*32 + j2*16
    const int b_col8 = (g & 1) * 8;                  // + s*16

    for (int c = 0; c < NCHUNK; c++) {
        const int k0 = c * KC;
        // ---- W tile: 128 v-rows x 32 k (fp32 -> bf16 hi/lo) ----
        #pragma unroll
        for (int it = 0; it < 4; it++) {
            int idx = tid + it * 256;          // 1024 float4 slots
            int r = idx >> 3, q = idx & 7;
            int gk = k0 + q * 4;
            int vr = v0 + r; if (vr >= Vn) vr = Vn - 1;
            float4 w = make_float4(0.f, 0.f, 0.f, 0.f);
            if (gk < CDIM) w = *(const float4*)(Wout + (size_t)vr * CDIM + gk);
            uint32_t h01, l01, h23, l23;
            split2t(w.x, w.y, h01, l01);
            split2t(w.z, w.w, h23, l23);
            uint32_t off = (uint32_t)(r * WSTR + q * 4) * 2;
            *(uint32_t*)((char*)sWhi + off)     = h01;
            *(uint32_t*)((char*)sWhi + off + 4) = h23;
            *(uint32_t*)((char*)sWlo + off)     = l01;
            *(uint32_t*)((char*)sWlo + off + 4) = l23;
        }
        // ---- X tile: 64 b-rows x 32 k ----
        #pragma unroll
        for (int it = 0; it < 2; it++) {
            int idx = tid + it * 256;          // 512 float4 slots
            int r = idx >> 3, q = idx & 7;
            int gk = k0 + q * 4;
            float4 x = make_float4(0.f, 0.f, 0.f, 0.f);
            if (gk < CDIM) x = *(const float4*)(g_xcat + (size_t)r * CDIM + gk);
            uint32_t h01, l01, h23, l23;
            split2t(x.x, x.y, h01, l01);
            split2t(x.z, x.w, h23, l23);
            uint32_t off = (uint32_t)(r * WSTR + q * 4) * 2;
            *(uint32_t*)((char*)sXhi + off)     = h01;
            *(uint32_t*)((char*)sXhi + off + 4) = h23;
            *(uint32_t*)((char*)sXlo + off)     = l01;
            *(uint32_t*)((char*)sXlo + off + 4) = l23;
        }
        __syncthreads();

        #pragma unroll
        for (int s = 0; s < 2; s++) {
            uint32_t ah[2][4], al[2][4];
            #pragma unroll
            for (int i = 0; i < 2; i++) {
                uint32_t off = (uint32_t)((wm * 32 + i * 16 + a_row) * WSTR
                                          + s * 16 + a_col8) * 2;
                ldmx4(ah[i], bWhi + off);
                ldmx4(al[i], bWlo + off);
            }
            uint32_t bh[2][4], bl[2][4];
            #pragma unroll
            for (int j2 = 0; j2 < 2; j2++) {
                uint32_t off = (uint32_t)((wn * 32 + j2 * 16 + b_row) * WSTR
                                          + s * 16 + b_col8) * 2;
                ldmx4(bh[j2], bXhi + off);
                ldmx4(bl[j2], bXlo + off);
            }
            #pragma unroll
            for (int i = 0; i < 2; i++)
                #pragma unroll
                for (int j = 0; j < 4; j++) {
                    const uint32_t* Bh = &bh[j >> 1][(j & 1) * 2];
                    const uint32_t* Bl = &bl[j >> 1][(j & 1) * 2];
                    mma16816(acc[i][j], ah[i], Bh);   // hi*hi
                    mma16816(acc[i][j], ah[i], Bl);   // hi*lo
                    mma16816(acc[i][j], al[i], Bh);   // lo*hi
                }
        }
        __syncthreads();
    }

    // ---- epilogue: C fragment -> gmem ----
    const int tq = lane & 3, tr = lane >> 2;
    #pragma unroll
    for (int i = 0; i < 2; i++) {
        int v1 = v0 + wm * 32 + i * 16 + tr;
        int v2 = v1 + 8;
        float bo1 = (v1 < Vn) ? bout[v1] : 0.f;
        float bo2 = (v2 < Vn) ? bout[v2] : 0.f;
        #pragma unroll
        for (int j = 0; j < 4; j++) {
            int bb = wn * 32 + j * 8 + tq * 2;
            if (v1 < Vn) {
                pred[(size_t)bb * Vn + v1]       = acc[i][j][0] + bo1;
                pred[(size_t)(bb + 1) * Vn + v1] = acc[i][j][1] + bo1;
            }
            if (v2 < Vn) {
                pred[(size_t)bb * Vn + v2]       = acc[i][j][2] + bo2;
                pred[(size_t)(bb + 1) * Vn + v2] = acc[i][j][3] + bo2;
            }
        }
    }
}

// ---------------- launch ----------------
extern "C" void kernel_launch(void* const* d_in, const int* in_sizes, int n_in,
                              void* d_out, int out_size) {
    const int*   ids    = (const int*)  d_in[0];
    const float* hidden = (const float*)d_in[1];
    const float* enc    = (const float*)d_in[2];
    const int*   mask   = (const int*)  d_in[3];
    const float* table  = (const float*)d_in[4];
    const float* Wa     = (const float*)d_in[5];
    const float* ba     = (const float*)d_in[6];
    const float* vw     = (const float*)d_in[7];
    const float* Wih    = (const float*)d_in[8];
    const float* Whh    = (const float*)d_in[9];
    const float* bih    = (const float*)d_in[10];
    const float* bhh    = (const float*)d_in[11];
    const float* Wout   = (const float*)d_in[12];
    const float* bout   = (const float*)d_in[13];
    float* out = (float*)d_out;

    float* d_hidpart; cudaGetSymbolAddress((void**)&d_hidpart, g_hidpart);
    float* d_xin;     cudaGetSymbolAddress((void**)&d_xin,     g_xin);
    float* d_gx;      cudaGetSymbolAddress((void**)&d_gx,      g_gx);
    float* d_gh;      cudaGetSymbolAddress((void**)&d_gh,      g_gh);

    k_emb<<<(Bn * En + 255) / 256, 256>>>(ids, table);
    k_gemm_small<<<Hn / 128, 256>>>(hidden, Hn, Hn, Wa, H3n, ba, d_hidpart, Hn);
    k_energy<<<dim3(4, Bn), 256>>>(enc, Wa, vw);
    k_softmax<<<Bn, Sn>>>(mask, out);
    k_weighted<<<dim3(H2n / 256, Bn), 256>>>(enc);
    k_xin<<<(Bn * XDIM + 255) / 256, 256>>>();
    k_gemm_small<<<H3n / 128, 256>>>(d_xin, XDIM, XDIM, Wih, XDIM, bih, d_gx, H3n);
    k_gemm_small<<<H3n / 128, 256>>>(hidden, Hn, Hn, Whh, Hn, bhh, d_gh, H3n);
    k_gru_concat<<<(Bn * CDIM + 255) / 256, 256>>>(hidden, out);
    k_out_mma<<<(Vn + 127) / 128, 256>>>(Wout, bout, out + PRED_OFF);
}

// round 6
// speedup vs baseline: 2.9426x; 1.2352x over previous
#include <cuda_runtime.h>
#include <cuda_bf16.h>
#include <math.h>
#include <stdint.h>

#define Bn 64
#define Sn 128
#define Hn 512
#define En 300
#define Vn 50257
#define H2n 1024
#define H3n 1536
#define XDIM 1324         // E + 2H
#define CDIM 1836         // 3H + E
#define NEGV -1e10f

#define PRED_OFF 0
#define HN_OFF   ((size_t)Bn * Vn)
#define A_OFF    (HN_OFF + (size_t)Bn * Hn)

// ---------------- scratch ----------------
__device__ __align__(16) float g_emb[Bn * En];
__device__ __align__(16) float g_hidpart[Bn * Hn];
__device__ __align__(16) float g_scorep[Bn * 8 * Sn];
__device__ __align__(16) float g_attn[Bn * Sn];
__device__ __align__(16) float g_weighted[Bn * H2n];
__device__ __align__(16) float g_xin[Bn * XDIM];
__device__ __align__(16) float g_gx[Bn * H3n];
__device__ __align__(16) float g_gh[Bn * H3n];
__device__ __align__(16) float g_xcat[Bn * CDIM];

// ---------------- helpers ----------------
__device__ __forceinline__ uint32_t smem_u32(const void* p) {
    uint32_t a;
    asm("{ .reg .u64 t; cvta.to.shared.u64 t, %1; cvt.u32.u64 %0, t; }" : "=r"(a) : "l"(p));
    return a;
}
__device__ __forceinline__ float2 lds2(uint32_t a) {
    float2 v;
    asm volatile("ld.shared.v2.f32 {%0,%1}, [%2];" : "=f"(v.x), "=f"(v.y) : "r"(a));
    return v;
}
__device__ __forceinline__ void cpa_cg(uint32_t dst, const void* src, int bytes) {
    asm volatile("cp.async.cg.shared.global [%0], [%1], 16, %2;"
                 :: "r"(dst), "l"(src), "r"(bytes) : "memory");
}
__device__ __forceinline__ void cpa_ca(uint32_t dst, const void* src, int bytes) {
    asm volatile("cp.async.ca.shared.global [%0], [%1], 16, %2;"
                 :: "r"(dst), "l"(src), "r"(bytes) : "memory");
}
#define CPA_COMMIT() asm volatile("cp.async.commit_group;" ::: "memory")
#define CPA_WAIT1()  asm volatile("cp.async.wait_group 1;" ::: "memory")

__device__ __forceinline__ void mma16816(float* c, const uint32_t* a, const uint32_t* b) {
    asm volatile("mma.sync.aligned.m16n8k16.row.col.f32.bf16.bf16.f32 "
                 "{%0,%1,%2,%3}, {%4,%5,%6,%7}, {%8,%9}, {%0,%1,%2,%3};"
                 : "+f"(c[0]), "+f"(c[1]), "+f"(c[2]), "+f"(c[3])
                 : "r"(a[0]), "r"(a[1]), "r"(a[2]), "r"(a[3]), "r"(b[0]), "r"(b[1]));
}
// truncation hi/lo split of two floats -> packed bf16x2 words
__device__ __forceinline__ void split2t(float x, float y, uint32_t& hiw, uint32_t& low) {
    uint32_t xb = __float_as_uint(x), yb = __float_as_uint(y);
    uint32_t hx = xb & 0xFFFF0000u, hy = yb & 0xFFFF0000u;
    hiw = (hx >> 16) | hy;
    float lx = x - __uint_as_float(hx);
    float ly = y - __uint_as_float(hy);
    asm("cvt.rn.bf16x2.f32 %0, %1, %2;" : "=r"(low) : "f"(ly), "f"(lx));
}
// swizzled fp32 tile address: rows of 32 floats (128B), 16B chunks XOR (row&7)
__device__ __forceinline__ uint32_t swaddr(int row, int k) {
    return (uint32_t)(row * 128 + ((((k >> 2) ^ (row & 7)) << 4)) + (k & 3) * 4);
}

// ---------------- 1) embedding gather ----------------
__global__ void k_emb(const int* __restrict__ ids, const float* __restrict__ table) {
    int idx = blockIdx.x * blockDim.x + threadIdx.x;
    if (idx >= Bn * En) return;
    int b = idx / En, e = idx - b * En;
    g_emb[idx] = table[(size_t)ids[b] * En + e];
}

// ---------------- small GEMM (fp32) ----------------
__global__ __launch_bounds__(256)
void k_gemm_small(const float* __restrict__ A, int astride, int K,
                  const float* __restrict__ W, int wstride,
                  const float* __restrict__ bias,
                  float* __restrict__ out, int ostride) {
    const int j0 = blockIdx.x * 128;
    __shared__ __align__(16) float As[32][68];
    __shared__ __align__(16) float Ws[32][132];
    const int tid = threadIdx.x;
    const int tx = tid & 15, ty = tid >> 4;
    float acc[4][8];
    #pragma unroll
    for (int i = 0; i < 4; i++)
        #pragma unroll
        for (int j = 0; j < 8; j++) acc[i][j] = 0.f;

    for (int k0 = 0; k0 < K; k0 += 32) {
        #pragma unroll
        for (int it = 0; it < 8; it++) {
            int idx = tid + it * 256;
            int b = idx >> 5, k = idx & 31;
            As[k][b] = (k0 + k < K) ? A[(size_t)b * astride + k0 + k] : 0.f;
        }
        #pragma unroll
        for (int it = 0; it < 16; it++) {
            int idx = tid + it * 256;
            int j = idx >> 5, k = idx & 31;
            Ws[k][j] = (k0 + k < K) ? W[(size_t)(j0 + j) * wstride + k0 + k] : 0.f;
        }
        __syncthreads();
        #pragma unroll
        for (int kk = 0; kk < 32; kk++) {
            float a[4], w[8];
            #pragma unroll
            for (int i = 0; i < 4; i++) a[i] = As[kk][ty * 4 + i];
            #pragma unroll
            for (int j = 0; j < 8; j++) w[j] = Ws[kk][tx * 8 + j];
            #pragma unroll
            for (int i = 0; i < 4; i++)
                #pragma unroll
                for (int j = 0; j < 8; j++) acc[i][j] += a[i] * w[j];
        }
        __syncthreads();
    }
    #pragma unroll
    for (int i = 0; i < 4; i++) {
        int b = ty * 4 + i;
        #pragma unroll
        for (int j = 0; j < 8; j++) {
            int jj = j0 + tx * 8 + j;
            out[(size_t)b * ostride + jj] = acc[i][j] + bias[jj];
        }
    }
}

// ---------------- 3) energy GEMM on HMMA + fused v*tanh score ----------------
// Block = (hchunk, b). M=128(s) x N=64(h), K=1024, chunks of 32, 3-stage cp.async.
// Warp layout: 8 warps = 4(wm over s) x 2(wn over h), 32x32 warp tiles -> full 128x64.
#define NCHE 32
#define STAGE_E 24576     // A 16KB + B 8KB
#define SMEM_E  (3 * STAGE_E)

__device__ __forceinline__ void pf_energy(int c, int st, uint32_t sbase,
                                          const float* enc, const float* Wa,
                                          int b, int h0, int tid) {
    if (c >= NCHE) return;
    int k0 = c * 32;
    uint32_t ab = sbase + st * STAGE_E;
    uint32_t bb = ab + 16384;
    #pragma unroll
    for (int it = 0; it < 4; it++) {
        int m = tid + it * 256;
        int row = m >> 3, kc = m & 7;
        cpa_cg(ab + row * 128 + (((kc ^ (row & 7)) << 4)),
               enc + ((size_t)(row * Bn + b)) * H2n + k0 + kc * 4, 16);
    }
    #pragma unroll
    for (int it = 0; it < 2; it++) {
        int m = tid + it * 256;
        int row = m >> 3, kc = m & 7;
        cpa_cg(bb + row * 128 + (((kc ^ (row & 7)) << 4)),
               Wa + (size_t)(h0 + row) * H3n + Hn + k0 + kc * 4, 16);
    }
}

__global__ __launch_bounds__(256, 2)
void k_energy_mma(const float* __restrict__ enc, const float* __restrict__ Wa,
                  const float* __restrict__ vw) {
    extern __shared__ __align__(16) char dsm[];
    const uint32_t sbase = smem_u32(dsm);
    __shared__ float s_hid[64];
    __shared__ float s_vw[64];
    __shared__ float s_red[128][2];

    const int tid = threadIdx.x;
    const int lane = tid & 31, wid = tid >> 5;
    const int wm = wid >> 1, wn = wid & 1;
    const int gq = lane >> 2, tq = lane & 3;
    const int hc = blockIdx.x, b = blockIdx.y;
    const int h0 = hc * 64;

    if (tid < 64) {
        s_hid[tid] = g_hidpart[b * Hn + h0 + tid];
        s_vw[tid]  = vw[h0 + tid];
    }

    float acc[2][4][4];
    #pragma unroll
    for (int i = 0; i < 2; i++)
        #pragma unroll
        for (int j = 0; j < 4; j++)
            #pragma unroll
            for (int q = 0; q < 4; q++) acc[i][j][q] = 0.f;

    pf_energy(0, 0, sbase, enc, Wa, b, h0, tid); CPA_COMMIT();
    pf_energy(1, 1, sbase, enc, Wa, b, h0, tid); CPA_COMMIT();

    for (int c = 0; c < NCHE; c++) {
        CPA_WAIT1();
        __syncthreads();
        const int st = c % 3;
        const uint32_t ab = sbase + st * STAGE_E;
        const uint32_t bb = ab + 16384;
        #pragma unroll
        for (int s = 0; s < 2; s++) {
            const int kk = s * 16 + tq * 2;
            uint32_t ah[2][4], al[2][4];
            #pragma unroll
            for (int i = 0; i < 2; i++) {
                int r = wm * 32 + i * 16 + gq;
                float2 x0 = lds2(ab + swaddr(r, kk));
                float2 x1 = lds2(ab + swaddr(r + 8, kk));
                float2 x2 = lds2(ab + swaddr(r, kk + 8));
                float2 x3 = lds2(ab + swaddr(r + 8, kk + 8));
                split2t(x0.x, x0.y, ah[i][0], al[i][0]);
                split2t(x1.x, x1.y, ah[i][1], al[i][1]);
                split2t(x2.x, x2.y, ah[i][2], al[i][2]);
                split2t(x3.x, x3.y, ah[i][3], al[i][3]);
            }
            uint32_t bh[4][2], bl[4][2];
            #pragma unroll
            for (int j = 0; j < 4; j++) {
                int r = wn * 32 + j * 8 + gq;
                float2 y0 = lds2(bb + swaddr(r, kk));
                float2 y1 = lds2(bb + swaddr(r, kk + 8));
                split2t(y0.x, y0.y, bh[j][0], bl[j][0]);
                split2t(y1.x, y1.y, bh[j][1], bl[j][1]);
            }
            #pragma unroll
            for (int i = 0; i < 2; i++)
                #pragma unroll
                for (int j = 0; j < 4; j++) {
                    mma16816(acc[i][j], ah[i], bh[j]);
                    mma16816(acc[i][j], ah[i], bl[j]);
                    mma16816(acc[i][j], al[i], bh[j]);
                }
        }
        pf_energy(c + 2, (c + 2) % 3, sbase, enc, Wa, b, h0, tid);
        CPA_COMMIT();
    }

    // epilogue: p[s] = sum_h v[h]*tanh(acc + hidpart[h])
    #pragma unroll
    for (int i = 0; i < 2; i++) {
        float p1 = 0.f, p2 = 0.f;
        #pragma unroll
        for (int j = 0; j < 4; j++) {
            int hl = wn * 32 + j * 8 + tq * 2;
            float v0 = s_vw[hl], v1 = s_vw[hl + 1];
            float hp0 = s_hid[hl], hp1 = s_hid[hl + 1];
            p1 += v0 * tanhf(acc[i][j][0] + hp0) + v1 * tanhf(acc[i][j][1] + hp1);
            p2 += v0 * tanhf(acc[i][j][2] + hp0) + v1 * tanhf(acc[i][j][3] + hp1);
        }
        p1 += __shfl_xor_sync(0xffffffffu, p1, 1);
        p1 += __shfl_xor_sync(0xffffffffu, p1, 2);
        p2 += __shfl_xor_sync(0xffffffffu, p2, 1);
        p2 += __shfl_xor_sync(0xffffffffu, p2, 2);
        if (tq == 0) {
            int s1 = wm * 32 + i * 16 + gq;
            s_red[s1][wn] = p1;
            s_red[s1 + 8][wn] = p2;
        }
    }
    __syncthreads();
    if (tid < 128)
        g_scorep[(b * 8 + hc) * Sn + tid] = s_red[tid][0] + s_red[tid][1];
}

// ---------------- 4) softmax ----------------
__global__ void k_softmax(const int* __restrict__ mask, float* __restrict__ out_a) {
    int b = blockIdx.x, s = threadIdx.x;
    float v = 0.f;
    #pragma unroll
    for (int c = 0; c < 8; c++) v += g_scorep[(b * 8 + c) * Sn + s];
    if (mask[b * Sn + s] == 0) v = NEGV;
    __shared__ float red[128];
    red[s] = v; __syncthreads();
    #pragma unroll
    for (int off = 64; off > 0; off >>= 1) {
        if (s < off) red[s] = fmaxf(red[s], red[s + off]);
        __syncthreads();
    }
    float m = red[0]; __syncthreads();
    float e = expf(v - m);
    red[s] = e; __syncthreads();
    #pragma unroll
    for (int off = 64; off > 0; off >>= 1) {
        if (s < off) red[s] += red[s + off];
        __syncthreads();
    }
    float a = e / red[0];
    g_attn[b * Sn + s] = a;
    out_a[A_OFF + b * Sn + s] = a;
}

// ---------------- 5) weighted ----------------
__global__ void k_weighted(const float* __restrict__ enc) {
    int b = blockIdx.y;
    int e = blockIdx.x * 256 + threadIdx.x;
    __shared__ float as[Sn];
    if (threadIdx.x < Sn) as[threadIdx.x] = g_attn[b * Sn + threadIdx.x];
    __syncthreads();
    float acc = 0.f;
    #pragma unroll 4
    for (int s = 0; s < Sn; s++)
        acc += as[s] * enc[((size_t)(s * Bn + b)) * H2n + e];
    g_weighted[b * H2n + e] = acc;
}

// ---------------- 6) x = [emb | weighted] ----------------
__global__ void k_xin() {
    int idx = blockIdx.x * blockDim.x + threadIdx.x;
    if (idx >= Bn * XDIM) return;
    int b = idx / XDIM, c = idx - b * XDIM;
    g_xin[idx] = (c < En) ? g_emb[b * En + c] : g_weighted[b * H2n + (c - En)];
}

// ---------------- 7) gates + h_new + xcat ----------------
__global__ void k_gru_concat(const float* __restrict__ hidden, float* __restrict__ out) {
    int idx = blockIdx.x * blockDim.x + threadIdx.x;
    if (idx >= Bn * CDIM) return;
    int b = idx / CDIM, c = idx - b * CDIM;
    if (c < Hn) {
        float r = 1.f / (1.f + expf(-(g_gx[b * H3n + c] + g_gh[b * H3n + c])));
        float z = 1.f / (1.f + expf(-(g_gx[b * H3n + Hn + c] + g_gh[b * H3n + Hn + c])));
        float n = tanhf(g_gx[b * H3n + 2 * Hn + c] + r * g_gh[b * H3n + 2 * Hn + c]);
        float hn = (1.f - z) * n + z * hidden[(size_t)b * Hn + c];
        out[HN_OFF + b * Hn + c] = hn;
        g_xcat[idx] = hn;
    } else if (c < Hn + H2n) {
        g_xcat[idx] = g_weighted[b * H2n + (c - Hn)];
    } else {
        g_xcat[idx] = g_emb[b * En + (c - Hn - H2n)];
    }
}

// ---------------- 8) output GEMM on HMMA, cp.async 3-stage ----------------
#define NCHO 58            // ceil(1836/32)
#define STAGE_O 24576      // W 16KB + X 8KB
#define SMEM_O  (3 * STAGE_O)

__device__ __forceinline__ void pf_out(int c, int st, uint32_t sbase,
                                       const float* Wout, int v0, int tid) {
    if (c >= NCHO) return;
    int k0 = c * 32;
    uint32_t wb = sbase + st * STAGE_O;
    uint32_t xb = wb + 16384;
    #pragma unroll
    for (int it = 0; it < 4; it++) {
        int m = tid + it * 256;
        int row = m >> 3, kc = m & 7;
        int vr = v0 + row; if (vr >= Vn) vr = Vn - 1;
        int gk = k0 + kc * 4;
        int rem = CDIM - gk;
        int bytes = rem >= 4 ? 16 : (rem > 0 ? rem * 4 : 0);
        int gko = rem > 0 ? gk : 0;
        cpa_cg(wb + row * 128 + (((kc ^ (row & 7)) << 4)),
               Wout + (size_t)vr * CDIM + gko, bytes);
    }
    #pragma unroll
    for (int it = 0; it < 2; it++) {
        int m = tid + it * 256;
        int row = m >> 3, kc = m & 7;
        int gk = k0 + kc * 4;
        int rem = CDIM - gk;
        int bytes = rem >= 4 ? 16 : (rem > 0 ? rem * 4 : 0);
        int gko = rem > 0 ? gk : 0;
        cpa_ca(xb + row * 128 + (((kc ^ (row & 7)) << 4)),
               g_xcat + (size_t)row * CDIM + gko, bytes);
    }
}

__global__ __launch_bounds__(256, 2)
void k_out_mma(const float* __restrict__ Wout, const float* __restrict__ bout,
               float* __restrict__ pred) {
    extern __shared__ __align__(16) char dsm[];
    const uint32_t sbase = smem_u32(dsm);
    const int tid = threadIdx.x;
    const int lane = tid & 31, wid = tid >> 5;
    const int wm = wid >> 1, wn = wid & 1;
    const int gq = lane >> 2, tq = lane & 3;
    const int v0 = blockIdx.x * 128;

    float acc[2][4][4];
    #pragma unroll
    for (int i = 0; i < 2; i++)
        #pragma unroll
        for (int j = 0; j < 4; j++)
            #pragma unroll
            for (int q = 0; q < 4; q++) acc[i][j][q] = 0.f;

    pf_out(0, 0, sbase, Wout, v0, tid); CPA_COMMIT();
    pf_out(1, 1, sbase, Wout, v0, tid); CPA_COMMIT();

    for (int c = 0; c < NCHO; c++) {
        CPA_WAIT1();
        __syncthreads();
        const int st = c % 3;
        const uint32_t wb = sbase + st * STAGE_O;
        const uint32_t xb = wb + 16384;
        #pragma unroll
        for (int s = 0; s < 2; s++) {
            const int kk = s * 16 + tq * 2;
            uint32_t ah[2][4], al[2][4];
            #pragma unroll
            for (int i = 0; i < 2; i++) {
                int r = wm * 32 + i * 16 + gq;
                float2 x0 = lds2(wb + swaddr(r, kk));
                float2 x1 = lds2(wb + swaddr(r + 8, kk));
                float2 x2 = lds2(wb + swaddr(r, kk + 8));
                float2 x3 = lds2(wb + swaddr(r + 8, kk + 8));
                split2t(x0.x, x0.y, ah[i][0], al[i][0]);
                split2t(x1.x, x1.y, ah[i][1], al[i][1]);
                split2t(x2.x, x2.y, ah[i][2], al[i][2]);
                split2t(x3.x, x3.y, ah[i][3], al[i][3]);
            }
            uint32_t bh[4][2], bl[4][2];
            #pragma unroll
            for (int j = 0; j < 4; j++) {
                int r = wn * 32 + j * 8 + gq;
                float2 y0 = lds2(xb + swaddr(r, kk));
                float2 y1 = lds2(xb + swaddr(r, kk + 8));
                split2t(y0.x, y0.y, bh[j][0], bl[j][0]);
                split2t(y1.x, y1.y, bh[j][1], bl[j][1]);
            }
            #pragma unroll
            for (int i = 0; i < 2; i++)
                #pragma unroll
                for (int j = 0; j < 4; j++) {
                    mma16816(acc[i][j], ah[i], bh[j]);
                    mma16816(acc[i][j], ah[i], bl[j]);
                    mma16816(acc[i][j], al[i], bh[j]);
                }
        }
        pf_out(c + 2, (c + 2) % 3, sbase, Wout, v0, tid);
        CPA_COMMIT();
    }

    // epilogue
    #pragma unroll
    for (int i = 0; i < 2; i++) {
        int v1 = v0 + wm * 32 + i * 16 + gq;
        int v2 = v1 + 8;
        float bo1 = (v1 < Vn) ? bout[v1] : 0.f;
        float bo2 = (v2 < Vn) ? bout[v2] : 0.f;
        #pragma unroll
        for (int j = 0; j < 4; j++) {
            int bb = wn * 32 + j * 8 + tq * 2;
            if (v1 < Vn) {
                pred[(size_t)bb * Vn + v1]       = acc[i][j][0] + bo1;
                pred[(size_t)(bb + 1) * Vn + v1] = acc[i][j][1] + bo1;
            }
            if (v2 < Vn) {
                pred[(size_t)bb * Vn + v2]       = acc[i][j][2] + bo2;
                pred[(size_t)(bb + 1) * Vn + v2] = acc[i][j][3] + bo2;
            }
        }
    }
}

// ---------------- launch ----------------
extern "C" void kernel_launch(void* const* d_in, const int* in_sizes, int n_in,
                              void* d_out, int out_size) {
    const int*   ids    = (const int*)  d_in[0];
    const float* hidden = (const float*)d_in[1];
    const float* enc    = (const float*)d_in[2];
    const int*   mask   = (const int*)  d_in[3];
    const float* table  = (const float*)d_in[4];
    const float* Wa     = (const float*)d_in[5];
    const float* ba     = (const float*)d_in[6];
    const float* vw     = (const float*)d_in[7];
    const float* Wih    = (const float*)d_in[8];
    const float* Whh    = (const float*)d_in[9];
    const float* bih    = (const float*)d_in[10];
    const float* bhh    = (const float*)d_in[11];
    const float* Wout   = (const float*)d_in[12];
    const float* bout   = (const float*)d_in[13];
    float* out = (float*)d_out;

    float* d_hidpart; cudaGetSymbolAddress((void**)&d_hidpart, g_hidpart);
    float* d_xin;     cudaGetSymbolAddress((void**)&d_xin,     g_xin);
    float* d_gx;      cudaGetSymbolAddress((void**)&d_gx,      g_gx);
    float* d_gh;      cudaGetSymbolAddress((void**)&d_gh,      g_gh);

    static int attr_done = 0;
    if (!attr_done) {
        cudaFuncSetAttribute(k_energy_mma, cudaFuncAttributeMaxDynamicSharedMemorySize, SMEM_E);
        cudaFuncSetAttribute(k_out_mma,    cudaFuncAttributeMaxDynamicSharedMemorySize, SMEM_O);
        attr_done = 1;
    }

    k_emb<<<(Bn * En + 255) / 256, 256>>>(ids, table);
    k_gemm_small<<<Hn / 128, 256>>>(hidden, Hn, Hn, Wa, H3n, ba, d_hidpart, Hn);
    k_energy_mma<<<dim3(8, Bn), 256, SMEM_E>>>(enc, Wa, vw);
    k_softmax<<<Bn, Sn>>>(mask, out);
    k_weighted<<<dim3(H2n / 256, Bn), 256>>>(enc);
    k_xin<<<(Bn * XDIM + 255) / 256, 256>>>();
    k_gemm_small<<<H3n / 128, 256>>>(d_xin, XDIM, XDIM, Wih, XDIM, bih, d_gx, H3n);
    k_gemm_small<<<H3n / 128, 256>>>(hidden, Hn, Hn, Whh, Hn, bhh, d_gh, H3n);
    k_gru_concat<<<(Bn * CDIM + 255) / 256, 256>>>(hidden, out);
    k_out_mma<<<(Vn + 127) / 128, 256, SMEM_O>>>(Wout, bout, out + PRED_OFF);
}

// round 8
// speedup vs baseline: 5.9022x; 2.0058x over previous
#include <cuda_runtime.h>
#include <cuda_bf16.h>
#include <math.h>
#include <stdint.h>

#define Bn 64
#define Sn 128
#define Hn 512
#define En 300
#define Vn 50257
#define H2n 1024
#define H3n 1536
#define XDIM 1324         // E + 2H
#define CDIM 1836         // 3H + E
#define CDIMP 1840        // padded to 16B-aligned bf16 rows
#define NEGV -1e10f

#define PRED_OFF 0
#define HN_OFF   ((size_t)Bn * Vn)
#define A_OFF    (HN_OFF + (size_t)Bn * Hn)

// ---------------- scratch ----------------
__device__ __align__(16) float g_emb[Bn * En];
__device__ __align__(16) float g_scorep[Bn * 8 * Sn];
__device__ __align__(16) float g_attn[Bn * Sn];
__device__ __align__(16) float g_weighted[Bn * H2n];
__device__ __align__(16) float g_xin[Bn * XDIM];
// split-K partials
__device__ __align__(16) float g_p_hid[4 * Bn * Hn];
__device__ __align__(16) float g_p_gx[4 * Bn * H3n];
__device__ __align__(16) float g_p_gh[4 * Bn * H3n];
// pre-split bf16 planes
__device__ __align__(16) __nv_bfloat16 g_enc_hi[(size_t)Sn * Bn * H2n];
__device__ __align__(16) __nv_bfloat16 g_enc_lo[(size_t)Sn * Bn * H2n];
__device__ __align__(16) __nv_bfloat16 g_wa_hi[Hn * H2n];   // Wa[:, Hn:] slab, [h][k]
__device__ __align__(16) __nv_bfloat16 g_wa_lo[Hn * H2n];
__device__ __align__(16) __nv_bfloat16 g_xcat_hi[Bn * CDIMP];
__device__ __align__(16) __nv_bfloat16 g_xcat_lo[Bn * CDIMP];

// ---------------- helpers ----------------
__device__ __forceinline__ uint32_t smem_u32(const void* p) {
    uint32_t a;
    asm("{ .reg .u64 t; cvta.to.shared.u64 t, %1; cvt.u32.u64 %0, t; }" : "=r"(a) : "l"(p));
    return a;
}
__device__ __forceinline__ float2 lds2(uint32_t a) {
    float2 v;
    asm volatile("ld.shared.v2.f32 {%0,%1}, [%2];" : "=f"(v.x), "=f"(v.y) : "r"(a));
    return v;
}
__device__ __forceinline__ void cpa_cg(uint32_t dst, const void* src, int bytes) {
    asm volatile("cp.async.cg.shared.global [%0], [%1], 16, %2;"
                 :: "r"(dst), "l"(src), "r"(bytes) : "memory");
}
#define CPA_COMMIT() asm volatile("cp.async.commit_group;" ::: "memory")
#define CPA_WAIT1()  asm volatile("cp.async.wait_group 1;" ::: "memory")

__device__ __forceinline__ void ldmx4(uint32_t* r, uint32_t addr) {
    asm volatile("ldmatrix.sync.aligned.m8n8.x4.shared.b16 {%0,%1,%2,%3}, [%4];"
                 : "=r"(r[0]), "=r"(r[1]), "=r"(r[2]), "=r"(r[3]) : "r"(addr));
}
__device__ __forceinline__ void mma16816(float* c, const uint32_t* a, const uint32_t* b) {
    asm volatile("mma.sync.aligned.m16n8k16.row.col.f32.bf16.bf16.f32 "
                 "{%0,%1,%2,%3}, {%4,%5,%6,%7}, {%8,%9}, {%0,%1,%2,%3};"
                 : "+f"(c[0]), "+f"(c[1]), "+f"(c[2]), "+f"(c[3])
                 : "r"(a[0]), "r"(a[1]), "r"(a[2]), "r"(a[3]), "r"(b[0]), "r"(b[1]));
}
// truncation hi/lo split of two floats -> packed bf16x2 words
__device__ __forceinline__ void split2t(float x, float y, uint32_t& hiw, uint32_t& low) {
    uint32_t xb = __float_as_uint(x), yb = __float_as_uint(y);
    uint32_t hx = xb & 0xFFFF0000u, hy = yb & 0xFFFF0000u;
    hiw = (hx >> 16) | hy;
    float lx = x - __uint_as_float(hx);
    float ly = y - __uint_as_float(hy);
    asm("cvt.rn.bf16x2.f32 %0, %1, %2;" : "=r"(low) : "f"(ly), "f"(lx));
}
// swizzled fp32 tile address: rows of 32 floats (128B), 16B chunks XOR (row&7)
__device__ __forceinline__ uint32_t swaddr(int row, int k) {
    return (uint32_t)(row * 128 + ((((k >> 2) ^ (row & 7)) << 4)) + (k & 3) * 4);
}

// ---------------- pre-split kernels ----------------
__global__ void k_split_enc(const float* __restrict__ enc) {
    size_t i4 = (size_t)blockIdx.x * 256 + threadIdx.x;
    if (i4 >= (size_t)Sn * Bn * H2n / 4) return;
    float4 v = ((const float4*)enc)[i4];
    uint32_t h01, l01, h23, l23;
    split2t(v.x, v.y, h01, l01);
    split2t(v.z, v.w, h23, l23);
    ((uint32_t*)g_enc_hi)[i4 * 2]     = h01;
    ((uint32_t*)g_enc_hi)[i4 * 2 + 1] = h23;
    ((uint32_t*)g_enc_lo)[i4 * 2]     = l01;
    ((uint32_t*)g_enc_lo)[i4 * 2 + 1] = l23;
}
__global__ void k_split_wa(const float* __restrict__ Wa) {
    int i4 = blockIdx.x * 256 + threadIdx.x;   // over 512*1024/4
    if (i4 >= Hn * H2n / 4) return;
    int h = i4 >> 8, k4 = i4 & 255;
    const float4 v = *(const float4*)(Wa + (size_t)h * H3n + Hn + k4 * 4);
    uint32_t h01, l01, h23, l23;
    split2t(v.x, v.y, h01, l01);
    split2t(v.z, v.w, h23, l23);
    int d = h * 512 + k4 * 2;                  // uint32 index into [h][k] plane
    ((uint32_t*)g_wa_hi)[d]     = h01;
    ((uint32_t*)g_wa_hi)[d + 1] = h23;
    ((uint32_t*)g_wa_lo)[d]     = l01;
    ((uint32_t*)g_wa_lo)[d + 1] = l23;
}

// ---------------- 1) embedding gather ----------------
__global__ void k_emb(const int* __restrict__ ids, const float* __restrict__ table) {
    int idx = blockIdx.x * blockDim.x + threadIdx.x;
    if (idx >= Bn * En) return;
    int b = idx / En, e = idx - b * En;
    g_emb[idx] = table[(size_t)ids[b] * En + e];
}

// ---------------- split-K partial GEMM ----------------
__global__ __launch_bounds__(256)
void k_gemm_part(const float* __restrict__ A, int astride, int K,
                 const float* __restrict__ W, int wstride,
                 float* __restrict__ outp, int ostride) {
    const int j0 = blockIdx.x * 64;
    const int kt = gridDim.y;
    const int ksl = (((K + kt - 1) / kt) + 31) & ~31;
    const int kb = blockIdx.y * ksl;
    const int ke = (K < kb + ksl) ? K : (kb + ksl);
    float* op = outp + (size_t)blockIdx.y * Bn * ostride;
    __shared__ float As[32][68];
    __shared__ float Ws[32][68];
    const int tid = threadIdx.x;
    const int tx = tid & 15, ty = tid >> 4;
    float acc[4][4];
    #pragma unroll
    for (int i = 0; i < 4; i++)
        #pragma unroll
        for (int j = 0; j < 4; j++) acc[i][j] = 0.f;

    for (int k0 = kb; k0 < ke; k0 += 32) {
        #pragma unroll
        for (int it = 0; it < 8; it++) {
            int idx = tid + it * 256;
            int b = idx >> 5, k = idx & 31;
            As[k][b] = (k0 + k < ke) ? A[(size_t)b * astride + k0 + k] : 0.f;
        }
        #pragma unroll
        for (int it = 0; it < 8; it++) {
            int idx = tid + it * 256;
            int j = idx >> 5, k = idx & 31;
            Ws[k][j] = (k0 + k < ke) ? W[(size_t)(j0 + j) * wstride + k0 + k] : 0.f;
        }
        __syncthreads();
        #pragma unroll
        for (int kk = 0; kk < 32; kk++) {
            float a[4], w[4];
            #pragma unroll
            for (int i = 0; i < 4; i++) a[i] = As[kk][ty * 4 + i];
            #pragma unroll
            for (int j = 0; j < 4; j++) w[j] = Ws[kk][tx * 4 + j];
            #pragma unroll
            for (int i = 0; i < 4; i++)
                #pragma unroll
                for (int j = 0; j < 4; j++) acc[i][j] += a[i] * w[j];
        }
        __syncthreads();
    }
    #pragma unroll
    for (int i = 0; i < 4; i++) {
        int b = ty * 4 + i;
        #pragma unroll
        for (int j = 0; j < 4; j++)
            op[(size_t)b * ostride + j0 + tx * 4 + j] = acc[i][j];
    }
}

// ---------------- 3) energy GEMM: pure ldmatrix+HMMA from pre-split planes ----------------
#define NCHE 32
#define STAGE_E 30720     // Ahi 10240 | Alo 10240 | Bhi 5120 | Blo 5120
#define SMEM_E  (3 * STAGE_E)

__device__ __forceinline__ void pf_energy(int c, int st, uint32_t sbase,
                                          int b, int h0, int tid) {
    if (c >= NCHE) return;
    int k0 = c * 32;
    uint32_t ab = sbase + st * STAGE_E;
    #pragma unroll
    for (int pl = 0; pl < 2; pl++) {
        const __nv_bfloat16* srcA = pl ? g_enc_lo : g_enc_hi;
        #pragma unroll
        for (int it = 0; it < 2; it++) {
            int idx = tid + it * 256;          // 512 = 128 rows x 4 chunks
            int row = idx >> 2, ch = idx & 3;
            cpa_cg(ab + pl * 10240 + row * 80 + ch * 16,
                   srcA + ((size_t)(row * Bn + b)) * H2n + k0 + ch * 8, 16);
        }
        const __nv_bfloat16* srcB = pl ? g_wa_lo : g_wa_hi;
        {
            int row = tid >> 2, ch = tid & 3;  // 256 = 64 rows x 4 chunks
            cpa_cg(ab + 20480 + pl * 5120 + row * 80 + ch * 16,
                   srcB + (size_t)(h0 + row) * H2n + k0 + ch * 8, 16);
        }
    }
}

__global__ __launch_bounds__(256, 2)
void k_energy_mma(const float* __restrict__ vw, const float* __restrict__ ba) {
    extern __shared__ __align__(16) char dsm[];
    const uint32_t sbase = smem_u32(dsm);
    __shared__ float s_hid[64];
    __shared__ float s_vw[64];
    __shared__ float s_red[128][2];

    const int tid = threadIdx.x;
    const int lane = tid & 31, wid = tid >> 5;
    const int wm = wid >> 1, wn = wid & 1;
    const int gq = lane >> 2, tq = lane & 3;
    const int hc = blockIdx.x, b = blockIdx.y;
    const int h0 = hc * 64;

    if (tid < 64) {
        float v = ba[h0 + tid];
        #pragma unroll
        for (int cc = 0; cc < 4; cc++)
            v += g_p_hid[((size_t)cc * Bn + b) * Hn + h0 + tid];
        s_hid[tid] = v;
        s_vw[tid]  = vw[h0 + tid];
    }

    const int a_row = lane & 15;
    const int a_col8 = (lane >> 4) * 8;
    const int g = lane >> 3;
    const int b_row = ((g >> 1) * 8) + (lane & 7);
    const int b_col8 = (g & 1) * 8;

    float acc[2][4][4];
    #pragma unroll
    for (int i = 0; i < 2; i++)
        #pragma unroll
        for (int j = 0; j < 4; j++)
            #pragma unroll
            for (int q = 0; q < 4; q++) acc[i][j][q] = 0.f;

    pf_energy(0, 0, sbase, b, h0, tid); CPA_COMMIT();
    pf_energy(1, 1, sbase, b, h0, tid); CPA_COMMIT();

    for (int c = 0; c < NCHE; c++) {
        CPA_WAIT1();
        __syncthreads();
        const int st = c % 3;
        const uint32_t ab = sbase + st * STAGE_E;
        #pragma unroll
        for (int s = 0; s < 2; s++) {
            uint32_t ah[2][4], al[2][4];
            #pragma unroll
            for (int i = 0; i < 2; i++) {
                uint32_t off = (uint32_t)((wm * 32 + i * 16 + a_row) * 80
                                          + (s * 16 + a_col8) * 2);
                ldmx4(ah[i], ab + off);
                ldmx4(al[i], ab + 10240 + off);
            }
            uint32_t bh2[2][4], bl2[2][4];
            #pragma unroll
            for (int j2 = 0; j2 < 2; j2++) {
                uint32_t off = (uint32_t)((wn * 32 + j2 * 16 + b_row) * 80
                                          + (s * 16 + b_col8) * 2);
                ldmx4(bh2[j2], ab + 20480 + off);
                ldmx4(bl2[j2], ab + 25600 + off);
            }
            #pragma unroll
            for (int i = 0; i < 2; i++)
                #pragma unroll
                for (int j = 0; j < 4; j++) {
                    const uint32_t* Bh = &bh2[j >> 1][(j & 1) * 2];
                    const uint32_t* Bl = &bl2[j >> 1][(j & 1) * 2];
                    mma16816(acc[i][j], ah[i], Bh);
                    mma16816(acc[i][j], ah[i], Bl);
                    mma16816(acc[i][j], al[i], Bh);
                }
        }
        pf_energy(c + 2, (c + 2) % 3, sbase, b, h0, tid);
        CPA_COMMIT();
    }

    #pragma unroll
    for (int i = 0; i < 2; i++) {
        float p1 = 0.f, p2 = 0.f;
        #pragma unroll
        for (int j = 0; j < 4; j++) {
            int hl = wn * 32 + j * 8 + tq * 2;
            float v0 = s_vw[hl], v1 = s_vw[hl + 1];
            float hp0 = s_hid[hl], hp1 = s_hid[hl + 1];
            p1 += v0 * tanhf(acc[i][j][0] + hp0) + v1 * tanhf(acc[i][j][1] + hp1);
            p2 += v0 * tanhf(acc[i][j][2] + hp0) + v1 * tanhf(acc[i][j][3] + hp1);
        }
        p1 += __shfl_xor_sync(0xffffffffu, p1, 1);
        p1 += __shfl_xor_sync(0xffffffffu, p1, 2);
        p2 += __shfl_xor_sync(0xffffffffu, p2, 1);
        p2 += __shfl_xor_sync(0xffffffffu, p2, 2);
        if (tq == 0) {
            int s1 = wm * 32 + i * 16 + gq;
            s_red[s1][wn] = p1;
            s_red[s1 + 8][wn] = p2;
        }
    }
    __syncthreads();
    if (tid < 128)
        g_scorep[(b * 8 + hc) * Sn + tid] = s_red[tid][0] + s_red[tid][1];
}

// ---------------- 4) softmax ----------------
__global__ void k_softmax(const int* __restrict__ mask, float* __restrict__ out_a) {
    int b = blockIdx.x, s = threadIdx.x;
    float v = 0.f;
    #pragma unroll
    for (int c = 0; c < 8; c++) v += g_scorep[(b * 8 + c) * Sn + s];
    if (mask[b * Sn + s] == 0) v = NEGV;
    __shared__ float red[128];
    red[s] = v; __syncthreads();
    #pragma unroll
    for (int off = 64; off > 0; off >>= 1) {
        if (s < off) red[s] = fmaxf(red[s], red[s + off]);
        __syncthreads();
    }
    float m = red[0]; __syncthreads();
    float e = expf(v - m);
    red[s] = e; __syncthreads();
    #pragma unroll
    for (int off = 64; off > 0; off >>= 1) {
        if (s < off) red[s] += red[s + off];
        __syncthreads();
    }
    float a = e / red[0];
    g_attn[b * Sn + s] = a;
    out_a[A_OFF + b * Sn + s] = a;
}

// ---------------- 5) weighted ----------------
__global__ void k_weighted(const float* __restrict__ enc) {
    int b = blockIdx.y;
    int e = blockIdx.x * 256 + threadIdx.x;
    __shared__ float as[Sn];
    if (threadIdx.x < Sn) as[threadIdx.x] = g_attn[b * Sn + threadIdx.x];
    __syncthreads();
    float acc = 0.f;
    #pragma unroll 4
    for (int s = 0; s < Sn; s++)
        acc += as[s] * enc[((size_t)(s * Bn + b)) * H2n + e];
    g_weighted[b * H2n + e] = acc;
}

// ---------------- 6) x = [emb | weighted] ----------------
__global__ void k_xin() {
    int idx = blockIdx.x * blockDim.x + threadIdx.x;
    if (idx >= Bn * XDIM) return;
    int b = idx / XDIM, c = idx - b * XDIM;
    g_xin[idx] = (c < En) ? g_emb[b * En + c] : g_weighted[b * H2n + (c - En)];
}

// ---------------- 7) gates + h_new + xcat (bf16 hi/lo planes, padded rows) ----------------
__global__ void k_gru_concat(const float* __restrict__ hidden,
                             const float* __restrict__ bih, const float* __restrict__ bhh,
                             float* __restrict__ out) {
    int idx = blockIdx.x * blockDim.x + threadIdx.x;
    if (idx >= Bn * CDIMP) return;
    int b = idx / CDIMP, c = idx - b * CDIMP;
    float val;
    if (c >= CDIM) {
        val = 0.f;
    } else if (c < Hn) {
        float gx0 = bih[c], gx1 = bih[Hn + c], gx2 = bih[2 * Hn + c];
        float gh0 = bhh[c], gh1 = bhh[Hn + c], gh2 = bhh[2 * Hn + c];
        #pragma unroll
        for (int cc = 0; cc < 4; cc++) {
            size_t base = ((size_t)cc * Bn + b) * H3n;
            gx0 += g_p_gx[base + c];
            gx1 += g_p_gx[base + Hn + c];
            gx2 += g_p_gx[base + 2 * Hn + c];
            gh0 += g_p_gh[base + c];
            gh1 += g_p_gh[base + Hn + c];
            gh2 += g_p_gh[base + 2 * Hn + c];
        }
        float r = 1.f / (1.f + expf(-(gx0 + gh0)));
        float z = 1.f / (1.f + expf(-(gx1 + gh1)));
        float n = tanhf(gx2 + r * gh2);
        val = (1.f - z) * n + z * hidden[(size_t)b * Hn + c];
        out[HN_OFF + b * Hn + c] = val;
    } else if (c < Hn + H2n) {
        val = g_weighted[b * H2n + (c - Hn)];
    } else {
        val = g_emb[b * En + (c - Hn - H2n)];
    }
    uint32_t xb = __float_as_uint(val) & 0xFFFF0000u;
    unsigned short ht = (unsigned short)(xb >> 16);
    g_xcat_hi[idx] = *reinterpret_cast<__nv_bfloat16*>(&ht);
    g_xcat_lo[idx] = __float2bfloat16_rn(val - __uint_as_float(xb));
}

// ---------------- 8) output GEMM: W fp32+regsplit, X bf16 planes via ldmatrix ----------------
#define NCHO 58            // ceil(1836/32)
#define STAGE_O 26624      // W fp32 16384 | Xhi 5120 | Xlo 5120
#define SMEM_O  (3 * STAGE_O)

__device__ __forceinline__ void pf_out(int c, int st, uint32_t sbase,
                                       const float* Wout, int v0, int tid) {
    if (c >= NCHO) return;
    int k0 = c * 32;
    uint32_t wb = sbase + st * STAGE_O;
    #pragma unroll
    for (int it = 0; it < 4; it++) {
        int m = tid + it * 256;
        int row = m >> 3, kc = m & 7;
        int vr = v0 + row; if (vr >= Vn) vr = Vn - 1;
        int gk = k0 + kc * 4;
        int rem = CDIM - gk;
        int bytes = rem >= 4 ? 16 : (rem > 0 ? rem * 4 : 0);
        int gko = rem > 0 ? gk : 0;
        cpa_cg(wb + row * 128 + (((kc ^ (row & 7)) << 4)),
               Wout + (size_t)vr * CDIM + gko, bytes);
    }
    #pragma unroll
    for (int pl = 0; pl < 2; pl++) {
        const __nv_bfloat16* src = pl ? g_xcat_lo : g_xcat_hi;
        int row = tid >> 2, ch = tid & 3;      // 256 = 64 rows x 4 chunks
        int gk = k0 + ch * 8;
        int rem = CDIMP - gk;
        int bytes = rem >= 8 ? 16 : (rem > 0 ? rem * 2 : 0);
        int gko = rem > 0 ? gk : 0;
        cpa_cg(wb + 16384 + pl * 5120 + row * 80 + ch * 16,
               src + (size_t)row * CDIMP + gko, bytes);
    }
}

__global__ __launch_bounds__(256, 2)
void k_out_mma(const float* __restrict__ Wout, const float* __restrict__ bout,
               float* __restrict__ pred) {
    extern __shared__ __align__(16) char dsm[];
    const uint32_t sbase = smem_u32(dsm);
    const int tid = threadIdx.x;
    const int lane = tid & 31, wid = tid >> 5;
    const int wm = wid >> 1, wn = wid & 1;
    const int gq = lane >> 2, tq = lane & 3;
    const int v0 = blockIdx.x * 128;
    const int g = lane >> 3;
    const int b_row = ((g >> 1) * 8) + (lane & 7);
    const int b_col8 = (g & 1) * 8;

    float acc[2][4][4];
    #pragma unroll
    for (int i = 0; i < 2; i++)
        #pragma unroll
        for (int j = 0; j < 4; j++)
            #pragma unroll
            for (int q = 0; q < 4; q++) acc[i][j][q] = 0.f;

    pf_out(0, 0, sbase, Wout, v0, tid); CPA_COMMIT();
    pf_out(1, 1, sbase, Wout, v0, tid); CPA_COMMIT();

    for (int c = 0; c < NCHO; c++) {
        CPA_WAIT1();
        __syncthreads();
        const int st = c % 3;
        const uint32_t wb = sbase + st * STAGE_O;
        #pragma unroll
        for (int s = 0; s < 2; s++) {
            const int kk = s * 16 + tq * 2;
            uint32_t ah[2][4], al[2][4];
            #pragma unroll
            for (int i = 0; i < 2; i++) {
                int r = wm * 32 + i * 16 + gq;
                float2 x0 = lds2(wb + swaddr(r, kk));
                float2 x1 = lds2(wb + swaddr(r + 8, kk));
                float2 x2 = lds2(wb + swaddr(r, kk + 8));
                float2 x3 = lds2(wb + swaddr(r + 8, kk + 8));
                split2t(x0.x, x0.y, ah[i][0], al[i][0]);
                split2t(x1.x, x1.y, ah[i][1], al[i][1]);
                split2t(x2.x, x2.y, ah[i][2], al[i][2]);
                split2t(x3.x, x3.y, ah[i][3], al[i][3]);
            }
            uint32_t bh2[2][4], bl2[2][4];
            #pragma unroll
            for (int j2 = 0; j2 < 2; j2++) {
                uint32_t off = (uint32_t)((wn * 32 + j2 * 16 + b_row) * 80
                                          + (s * 16 + b_col8) * 2);
                ldmx4(bh2[j2], wb + 16384 + off);
                ldmx4(bl2[j2], wb + 21504 + off);
            }
            #pragma unroll
            for (int i = 0; i < 2; i++)
                #pragma unroll
                for (int j = 0; j < 4; j++) {
                    const uint32_t* Bh = &bh2[j >> 1][(j & 1) * 2];
                    const uint32_t* Bl = &bl2[j >> 1][(j & 1) * 2];
                    mma16816(acc[i][j], ah[i], Bh);
                    mma16816(acc[i][j], ah[i], Bl);
                    mma16816(acc[i][j], al[i], Bh);
                }
        }
        pf_out(c + 2, (c + 2) % 3, sbase, Wout, v0, tid);
        CPA_COMMIT();
    }

    #pragma unroll
    for (int i = 0; i < 2; i++) {
        int v1 = v0 + wm * 32 + i * 16 + gq;
        int v2 = v1 + 8;
        float bo1 = (v1 < Vn) ? bout[v1] : 0.f;
        float bo2 = (v2 < Vn) ? bout[v2] : 0.f;
        #pragma unroll
        for (int j = 0; j < 4; j++) {
            int bb = wn * 32 + j * 8 + tq * 2;
            if (v1 < Vn) {
                pred[(size_t)bb * Vn + v1]       = acc[i][j][0] + bo1;
                pred[(size_t)(bb + 1) * Vn + v1] = acc[i][j][1] + bo1;
            }
            if (v2 < Vn) {
                pred[(size_t)bb * Vn + v2]       = acc[i][j][2] + bo2;
                pred[(size_t)(bb + 1) * Vn + v2] = acc[i][j][3] + bo2;
            }
        }
    }
}

// ---------------- launch ----------------
extern "C" void kernel_launch(void* const* d_in, const int* in_sizes, int n_in,
                              void* d_out, int out_size) {
    const int*   ids    = (const int*)  d_in[0];
    const float* hidden = (const float*)d_in[1];
    const float* enc    = (const float*)d_in[2];
    const int*   mask   = (const int*)  d_in[3];
    const float* table  = (const float*)d_in[4];
    const float* Wa     = (const float*)d_in[5];
    const float* ba     = (const float*)d_in[6];
    const float* vw     = (const float*)d_in[7];
    const float* Wih    = (const float*)d_in[8];
    const float* Whh    = (const float*)d_in[9];
    const float* bih    = (const float*)d_in[10];
    const float* bhh    = (const float*)d_in[11];
    const float* Wout   = (const float*)d_in[12];
    const float* bout   = (const float*)d_in[13];
    float* out = (float*)d_out;

    float* d_p_hid; cudaGetSymbolAddress((void**)&d_p_hid, g_p_hid);
    float* d_p_gx;  cudaGetSymbolAddress((void**)&d_p_gx,  g_p_gx);
    float* d_p_gh;  cudaGetSymbolAddress((void**)&d_p_gh,  g_p_gh);
    float* d_xin;   cudaGetSymbolAddress((void**)&d_xin,   g_xin);

    static int attr_done = 0;
    if (!attr_done) {
        cudaFuncSetAttribute(k_energy_mma, cudaFuncAttributeMaxDynamicSharedMemorySize, SMEM_E);
        cudaFuncSetAttribute(k_out_mma,    cudaFuncAttributeMaxDynamicSharedMemorySize, SMEM_O);
        attr_done = 1;
    }

    k_split_enc<<<(Sn * Bn * H2n / 4 + 255) / 256, 256>>>(enc);
    k_split_wa<<<(Hn * H2n / 4 + 255) / 256, 256>>>(Wa);
    k_emb<<<(Bn * En + 255) / 256, 256>>>(ids, table);
    k_gemm_part<<<dim3(Hn / 64, 4), 256>>>(hidden, Hn, Hn, Wa, H3n, d_p_hid, Hn);
    k_energy_mma<<<dim3(8, Bn), 256, SMEM_E>>>(vw, ba);
    k_softmax<<<Bn, Sn>>>(mask, out);
    k_weighted<<<dim3(H2n / 256, Bn), 256>>>(enc);
    k_xin<<<(Bn * XDIM + 255) / 256, 256>>>();
    k_gemm_part<<<dim3(H3n / 64, 4), 256>>>(d_xin, XDIM, XDIM, Wih, XDIM, d_p_gx, H3n);
    k_gemm_part<<<dim3(H3n / 64, 4), 256>>>(hidden, Hn, Hn, Whh, Hn, d_p_gh, H3n);
    k_gru_concat<<<(Bn * CDIMP + 255) / 256, 256>>>(hidden, bih, bhh, out);
    k_out_mma<<<(Vn + 127) / 128, 256, SMEM_O>>>(Wout, bout, out + PRED_OFF);
}

// round 9
// speedup vs baseline: 6.1053x; 1.0344x over previous
#include <cuda_runtime.h>
#include <cuda_bf16.h>
#include <math.h>
#include <stdint.h>

#define Bn 64
#define Sn 128
#define Hn 512
#define En 300
#define Vn 50257
#define H2n 1024
#define H3n 1536
#define XDIM 1324         // E + 2H
#define CDIM 1836         // 3H + E
#define CDIMP 1840        // padded to 16B-aligned bf16 rows
#define NEGV -1e10f
#define KT 8              // split-K factor for small GEMMs

#define PRED_OFF 0
#define HN_OFF   ((size_t)Bn * Vn)
#define A_OFF    (HN_OFF + (size_t)Bn * Hn)

// ---------------- scratch ----------------
__device__ __align__(16) float g_emb[Bn * En];
__device__ __align__(16) float g_scorep[Bn * 8 * Sn];
__device__ __align__(16) float g_attn[Bn * Sn];
__device__ __align__(16) float g_xin[Bn * XDIM];
// split-K partials
__device__ __align__(16) float g_p_hid[KT * Bn * Hn];
__device__ __align__(16) float g_p_gx[KT * Bn * H3n];
__device__ __align__(16) float g_p_gh[KT * Bn * H3n];
// pre-split bf16 planes
__device__ __align__(16) __nv_bfloat16 g_enc_hi[(size_t)Sn * Bn * H2n];
__device__ __align__(16) __nv_bfloat16 g_enc_lo[(size_t)Sn * Bn * H2n];
__device__ __align__(16) __nv_bfloat16 g_wa_hi[Hn * H2n];
__device__ __align__(16) __nv_bfloat16 g_wa_lo[Hn * H2n];
__device__ __align__(16) __nv_bfloat16 g_xcat_hi[Bn * CDIMP];
__device__ __align__(16) __nv_bfloat16 g_xcat_lo[Bn * CDIMP];

// ---------------- helpers ----------------
__device__ __forceinline__ uint32_t smem_u32(const void* p) {
    uint32_t a;
    asm("{ .reg .u64 t; cvta.to.shared.u64 t, %1; cvt.u32.u64 %0, t; }" : "=r"(a) : "l"(p));
    return a;
}
__device__ __forceinline__ float2 lds2(uint32_t a) {
    float2 v;
    asm volatile("ld.shared.v2.f32 {%0,%1}, [%2];" : "=f"(v.x), "=f"(v.y) : "r"(a));
    return v;
}
__device__ __forceinline__ void cpa_cg(uint32_t dst, const void* src, int bytes) {
    asm volatile("cp.async.cg.shared.global [%0], [%1], 16, %2;"
                 :: "r"(dst), "l"(src), "r"(bytes) : "memory");
}
#define CPA_COMMIT() asm volatile("cp.async.commit_group;" ::: "memory")
#define CPA_WAIT1()  asm volatile("cp.async.wait_group 1;" ::: "memory")
#define CPA_WAIT2()  asm volatile("cp.async.wait_group 2;" ::: "memory")

__device__ __forceinline__ void ldmx4(uint32_t* r, uint32_t addr) {
    asm volatile("ldmatrix.sync.aligned.m8n8.x4.shared.b16 {%0,%1,%2,%3}, [%4];"
                 : "=r"(r[0]), "=r"(r[1]), "=r"(r[2]), "=r"(r[3]) : "r"(addr));
}
__device__ __forceinline__ void mma16816(float* c, const uint32_t* a, const uint32_t* b) {
    asm volatile("mma.sync.aligned.m16n8k16.row.col.f32.bf16.bf16.f32 "
                 "{%0,%1,%2,%3}, {%4,%5,%6,%7}, {%8,%9}, {%0,%1,%2,%3};"
                 : "+f"(c[0]), "+f"(c[1]), "+f"(c[2]), "+f"(c[3])
                 : "r"(a[0]), "r"(a[1]), "r"(a[2]), "r"(a[3]), "r"(b[0]), "r"(b[1]));
}
__device__ __forceinline__ void split2t(float x, float y, uint32_t& hiw, uint32_t& low) {
    uint32_t xb = __float_as_uint(x), yb = __float_as_uint(y);
    uint32_t hx = xb & 0xFFFF0000u, hy = yb & 0xFFFF0000u;
    hiw = (hx >> 16) | hy;
    float lx = x - __uint_as_float(hx);
    float ly = y - __uint_as_float(hy);
    asm("cvt.rn.bf16x2.f32 %0, %1, %2;" : "=r"(low) : "f"(ly), "f"(lx));
}
__device__ __forceinline__ uint32_t swaddr(int row, int k) {
    return (uint32_t)(row * 128 + ((((k >> 2) ^ (row & 7)) << 4)) + (k & 3) * 4);
}
__device__ __forceinline__ void split_store(float val, int idx) {
    uint32_t xb = __float_as_uint(val) & 0xFFFF0000u;
    unsigned short ht = (unsigned short)(xb >> 16);
    g_xcat_hi[idx] = *reinterpret_cast<__nv_bfloat16*>(&ht);
    g_xcat_lo[idx] = __float2bfloat16_rn(val - __uint_as_float(xb));
}

// ---------------- pre-split kernels ----------------
__global__ void k_split_enc(const float* __restrict__ enc) {
    size_t i4 = (size_t)blockIdx.x * 256 + threadIdx.x;
    if (i4 >= (size_t)Sn * Bn * H2n / 4) return;
    float4 v = ((const float4*)enc)[i4];
    uint32_t h01, l01, h23, l23;
    split2t(v.x, v.y, h01, l01);
    split2t(v.z, v.w, h23, l23);
    ((uint32_t*)g_enc_hi)[i4 * 2]     = h01;
    ((uint32_t*)g_enc_hi)[i4 * 2 + 1] = h23;
    ((uint32_t*)g_enc_lo)[i4 * 2]     = l01;
    ((uint32_t*)g_enc_lo)[i4 * 2 + 1] = l23;
}
__global__ void k_split_wa(const float* __restrict__ Wa) {
    int i4 = blockIdx.x * 256 + threadIdx.x;
    if (i4 >= Hn * H2n / 4) return;
    int h = i4 >> 8, k4 = i4 & 255;
    const float4 v = *(const float4*)(Wa + (size_t)h * H3n + Hn + k4 * 4);
    uint32_t h01, l01, h23, l23;
    split2t(v.x, v.y, h01, l01);
    split2t(v.z, v.w, h23, l23);
    int d = h * 512 + k4 * 2;
    ((uint32_t*)g_wa_hi)[d]     = h01;
    ((uint32_t*)g_wa_hi)[d + 1] = h23;
    ((uint32_t*)g_wa_lo)[d]     = l01;
    ((uint32_t*)g_wa_lo)[d + 1] = l23;
}

// ---------------- 1) embedding gather ----------------
__global__ void k_emb(const int* __restrict__ ids, const float* __restrict__ table) {
    int idx = blockIdx.x * blockDim.x + threadIdx.x;
    if (idx >= Bn * En) return;
    int b = idx / En, e = idx - b * En;
    g_emb[idx] = table[(size_t)ids[b] * En + e];
}

// ---------------- split-K partial GEMM (j-tile 32, KT slices) ----------------
__global__ __launch_bounds__(256)
void k_gemm_part(const float* __restrict__ A, int astride, int K,
                 const float* __restrict__ W, int wstride,
                 float* __restrict__ outp, int ostride) {
    const int j0 = blockIdx.x * 32;
    const int kt = gridDim.y;
    const int ksl = (((K + kt - 1) / kt) + 31) & ~31;
    const int kb = blockIdx.y * ksl;
    const int ke = (K < kb + ksl) ? K : (kb + ksl);
    float* op = outp + (size_t)blockIdx.y * Bn * ostride;
    __shared__ float As[32][65];
    __shared__ float Ws[32][33];
    const int tid = threadIdx.x;
    const int tx = tid & 7, ty = tid >> 3;   // tx: 4 j, ty: 2 b
    float acc[2][4];
    #pragma unroll
    for (int i = 0; i < 2; i++)
        #pragma unroll
        for (int j = 0; j < 4; j++) acc[i][j] = 0.f;

    for (int k0 = kb; k0 < ke; k0 += 32) {
        #pragma unroll
        for (int it = 0; it < 8; it++) {
            int idx = tid + it * 256;
            int b = idx >> 5, k = idx & 31;
            As[k][b] = (k0 + k < ke) ? A[(size_t)b * astride + k0 + k] : 0.f;
        }
        #pragma unroll
        for (int it = 0; it < 4; it++) {
            int idx = tid + it * 256;
            int j = idx >> 5, k = idx & 31;
            Ws[k][j] = (k0 + k < ke) ? W[(size_t)(j0 + j) * wstride + k0 + k] : 0.f;
        }
        __syncthreads();
        #pragma unroll
        for (int kk = 0; kk < 32; kk++) {
            float a0 = As[kk][ty * 2], a1 = As[kk][ty * 2 + 1];
            float w[4];
            #pragma unroll
            for (int j = 0; j < 4; j++) w[j] = Ws[kk][tx * 4 + j];
            #pragma unroll
            for (int j = 0; j < 4; j++) {
                acc[0][j] += a0 * w[j];
                acc[1][j] += a1 * w[j];
            }
        }
        __syncthreads();
    }
    #pragma unroll
    for (int i = 0; i < 2; i++) {
        int b = ty * 2 + i;
        #pragma unroll
        for (int j = 0; j < 4; j++)
            op[(size_t)b * ostride + j0 + tx * 4 + j] = acc[i][j];
    }
}

// ---------------- 3) energy GEMM: ldmatrix+HMMA, 3-stage ----------------
#define NCHE 32
#define STAGE_E 30720
#define SMEM_E  (3 * STAGE_E)

__device__ __forceinline__ void pf_energy(int c, int st, uint32_t sbase,
                                          int b, int h0, int tid) {
    if (c >= NCHE) return;
    int k0 = c * 32;
    uint32_t ab = sbase + st * STAGE_E;
    #pragma unroll
    for (int pl = 0; pl < 2; pl++) {
        const __nv_bfloat16* srcA = pl ? g_enc_lo : g_enc_hi;
        #pragma unroll
        for (int it = 0; it < 2; it++) {
            int idx = tid + it * 256;
            int row = idx >> 2, ch = idx & 3;
            cpa_cg(ab + pl * 10240 + row * 80 + ch * 16,
                   srcA + ((size_t)(row * Bn + b)) * H2n + k0 + ch * 8, 16);
        }
        const __nv_bfloat16* srcB = pl ? g_wa_lo : g_wa_hi;
        {
            int row = tid >> 2, ch = tid & 3;
            cpa_cg(ab + 20480 + pl * 5120 + row * 80 + ch * 16,
                   srcB + (size_t)(h0 + row) * H2n + k0 + ch * 8, 16);
        }
    }
}

__global__ __launch_bounds__(256, 2)
void k_energy_mma(const float* __restrict__ vw, const float* __restrict__ ba) {
    extern __shared__ __align__(16) char dsm[];
    const uint32_t sbase = smem_u32(dsm);
    __shared__ float s_hid[64];
    __shared__ float s_vw[64];
    __shared__ float s_red[128][2];

    const int tid = threadIdx.x;
    const int lane = tid & 31, wid = tid >> 5;
    const int wm = wid >> 1, wn = wid & 1;
    const int gq = lane >> 2, tq = lane & 3;
    const int hc = blockIdx.x, b = blockIdx.y;
    const int h0 = hc * 64;

    if (tid < 64) {
        float v = ba[h0 + tid];
        #pragma unroll
        for (int cc = 0; cc < KT; cc++)
            v += g_p_hid[((size_t)cc * Bn + b) * Hn + h0 + tid];
        s_hid[tid] = v;
        s_vw[tid]  = vw[h0 + tid];
    }

    const int a_row = lane & 15;
    const int a_col8 = (lane >> 4) * 8;
    const int g = lane >> 3;
    const int b_row = ((g >> 1) * 8) + (lane & 7);
    const int b_col8 = (g & 1) * 8;

    float acc[2][4][4];
    #pragma unroll
    for (int i = 0; i < 2; i++)
        #pragma unroll
        for (int j = 0; j < 4; j++)
            #pragma unroll
            for (int q = 0; q < 4; q++) acc[i][j][q] = 0.f;

    pf_energy(0, 0, sbase, b, h0, tid); CPA_COMMIT();
    pf_energy(1, 1, sbase, b, h0, tid); CPA_COMMIT();

    for (int c = 0; c < NCHE; c++) {
        CPA_WAIT1();
        __syncthreads();
        const int st = c % 3;
        const uint32_t ab = sbase + st * STAGE_E;
        #pragma unroll
        for (int s = 0; s < 2; s++) {
            uint32_t ah[2][4], al[2][4];
            #pragma unroll
            for (int i = 0; i < 2; i++) {
                uint32_t off = (uint32_t)((wm * 32 + i * 16 + a_row) * 80
                                          + (s * 16 + a_col8) * 2);
                ldmx4(ah[i], ab + off);
                ldmx4(al[i], ab + 10240 + off);
            }
            uint32_t bh2[2][4], bl2[2][4];
            #pragma unroll
            for (int j2 = 0; j2 < 2; j2++) {
                uint32_t off = (uint32_t)((wn * 32 + j2 * 16 + b_row) * 80
                                          + (s * 16 + b_col8) * 2);
                ldmx4(bh2[j2], ab + 20480 + off);
                ldmx4(bl2[j2], ab + 25600 + off);
            }
            #pragma unroll
            for (int i = 0; i < 2; i++)
                #pragma unroll
                for (int j = 0; j < 4; j++) {
                    const uint32_t* Bh = &bh2[j >> 1][(j & 1) * 2];
                    const uint32_t* Bl = &bl2[j >> 1][(j & 1) * 2];
                    mma16816(acc[i][j], ah[i], Bh);
                    mma16816(acc[i][j], ah[i], Bl);
                    mma16816(acc[i][j], al[i], Bh);
                }
        }
        pf_energy(c + 2, (c + 2) % 3, sbase, b, h0, tid);
        CPA_COMMIT();
    }

    #pragma unroll
    for (int i = 0; i < 2; i++) {
        float p1 = 0.f, p2 = 0.f;
        #pragma unroll
        for (int j = 0; j < 4; j++) {
            int hl = wn * 32 + j * 8 + tq * 2;
            float v0 = s_vw[hl], v1 = s_vw[hl + 1];
            float hp0 = s_hid[hl], hp1 = s_hid[hl + 1];
            p1 += v0 * tanhf(acc[i][j][0] + hp0) + v1 * tanhf(acc[i][j][1] + hp1);
            p2 += v0 * tanhf(acc[i][j][2] + hp0) + v1 * tanhf(acc[i][j][3] + hp1);
        }
        p1 += __shfl_xor_sync(0xffffffffu, p1, 1);
        p1 += __shfl_xor_sync(0xffffffffu, p1, 2);
        p2 += __shfl_xor_sync(0xffffffffu, p2, 1);
        p2 += __shfl_xor_sync(0xffffffffu, p2, 2);
        if (tq == 0) {
            int s1 = wm * 32 + i * 16 + gq;
            s_red[s1][wn] = p1;
            s_red[s1 + 8][wn] = p2;
        }
    }
    __syncthreads();
    if (tid < 128)
        g_scorep[(b * 8 + hc) * Sn + tid] = s_red[tid][0] + s_red[tid][1];
}

// ---------------- 4) fused softmax + weighted + xin + xcat(weighted/emb) ----------------
__global__ __launch_bounds__(256)
void k_attn_ctx(const int* __restrict__ mask, const float* __restrict__ enc,
                float* __restrict__ out_a) {
    const int b = blockIdx.x;
    const int tid = threadIdx.x;
    __shared__ float red[128];
    __shared__ float a_s[Sn];

    float v = 0.f;
    if (tid < 128) {
        #pragma unroll
        for (int c = 0; c < 8; c++) v += g_scorep[(b * 8 + c) * Sn + tid];
        if (mask[b * Sn + tid] == 0) v = NEGV;
        red[tid] = v;
    }
    __syncthreads();
    #pragma unroll
    for (int off = 64; off > 0; off >>= 1) {
        if (tid < off) red[tid] = fmaxf(red[tid], red[tid + off]);
        __syncthreads();
    }
    float m = red[0];
    __syncthreads();
    float e = 0.f;
    if (tid < 128) { e = expf(v - m); red[tid] = e; }
    __syncthreads();
    #pragma unroll
    for (int off = 64; off > 0; off >>= 1) {
        if (tid < off) red[tid] += red[tid + off];
        __syncthreads();
    }
    if (tid < 128) {
        float a = e / red[0];
        a_s[tid] = a;
        g_attn[b * Sn + tid] = a;
        out_a[A_OFF + b * Sn + tid] = a;
    }
    __syncthreads();

    // weighted[b, e0..e0+3]
    const int e0 = tid * 4;
    float4 acc = make_float4(0.f, 0.f, 0.f, 0.f);
    #pragma unroll 4
    for (int s = 0; s < Sn; s++) {
        float a = a_s[s];
        float4 ev = *(const float4*)(enc + ((size_t)(s * Bn + b)) * H2n + e0);
        acc.x += a * ev.x; acc.y += a * ev.y; acc.z += a * ev.z; acc.w += a * ev.w;
    }
    *(float4*)(g_xin + (size_t)b * XDIM + En + e0) = acc;
    int cb = b * CDIMP + Hn + e0;
    split_store(acc.x, cb);
    split_store(acc.y, cb + 1);
    split_store(acc.z, cb + 2);
    split_store(acc.w, cb + 3);

    // emb copy into xin and xcat
    for (int idx = tid; idx < En; idx += 256) {
        float val = g_emb[b * En + idx];
        g_xin[(size_t)b * XDIM + idx] = val;
        split_store(val, b * CDIMP + Hn + H2n + idx);
    }
    // pad
    if (tid < CDIMP - CDIM) {
        g_xcat_hi[b * CDIMP + CDIM + tid] = __float2bfloat16_rn(0.f);
        g_xcat_lo[b * CDIMP + CDIM + tid] = __float2bfloat16_rn(0.f);
    }
}

// ---------------- 7) gates + h_new + xcat(h_new) ----------------
__global__ void k_gru(const float* __restrict__ hidden,
                      const float* __restrict__ bih, const float* __restrict__ bhh,
                      float* __restrict__ out) {
    int idx = blockIdx.x * blockDim.x + threadIdx.x;
    if (idx >= Bn * Hn) return;
    int b = idx / Hn, c = idx - b * Hn;
    float gx0 = bih[c], gx1 = bih[Hn + c], gx2 = bih[2 * Hn + c];
    float gh0 = bhh[c], gh1 = bhh[Hn + c], gh2 = bhh[2 * Hn + c];
    #pragma unroll
    for (int cc = 0; cc < KT; cc++) {
        size_t base = ((size_t)cc * Bn + b) * H3n;
        gx0 += g_p_gx[base + c];
        gx1 += g_p_gx[base + Hn + c];
        gx2 += g_p_gx[base + 2 * Hn + c];
        gh0 += g_p_gh[base + c];
        gh1 += g_p_gh[base + Hn + c];
        gh2 += g_p_gh[base + 2 * Hn + c];
    }
    float r = 1.f / (1.f + expf(-(gx0 + gh0)));
    float z = 1.f / (1.f + expf(-(gx1 + gh1)));
    float n = tanhf(gx2 + r * gh2);
    float val = (1.f - z) * n + z * hidden[(size_t)b * Hn + c];
    out[HN_OFF + b * Hn + c] = val;
    split_store(val, b * CDIMP + c);
}

// ---------------- 8) output GEMM: 4-stage pipeline ----------------
#define NCHO 58
#define STAGE_O 26624      // W fp32 16384 | Xhi 5120 | Xlo 5120
#define SMEM_O  (4 * STAGE_O)

__device__ __forceinline__ void pf_out(int c, int st, uint32_t sbase,
                                       const float* Wout, int v0, int tid) {
    if (c >= NCHO) return;
    int k0 = c * 32;
    uint32_t wb = sbase + st * STAGE_O;
    #pragma unroll
    for (int it = 0; it < 4; it++) {
        int m = tid + it * 256;
        int row = m >> 3, kc = m & 7;
        int vr = v0 + row; if (vr >= Vn) vr = Vn - 1;
        int gk = k0 + kc * 4;
        int rem = CDIM - gk;
        int bytes = rem >= 4 ? 16 : (rem > 0 ? rem * 4 : 0);
        int gko = rem > 0 ? gk : 0;
        cpa_cg(wb + row * 128 + (((kc ^ (row & 7)) << 4)),
               Wout + (size_t)vr * CDIM + gko, bytes);
    }
    #pragma unroll
    for (int pl = 0; pl < 2; pl++) {
        const __nv_bfloat16* src = pl ? g_xcat_lo : g_xcat_hi;
        int row = tid >> 2, ch = tid & 3;
        int gk = k0 + ch * 8;
        int rem = CDIMP - gk;
        int bytes = rem >= 8 ? 16 : (rem > 0 ? rem * 2 : 0);
        int gko = rem > 0 ? gk : 0;
        cpa_cg(wb + 16384 + pl * 5120 + row * 80 + ch * 16,
               src + (size_t)row * CDIMP + gko, bytes);
    }
}

__global__ __launch_bounds__(256, 2)
void k_out_mma(const float* __restrict__ Wout, const float* __restrict__ bout,
               float* __restrict__ pred) {
    extern __shared__ __align__(16) char dsm[];
    const uint32_t sbase = smem_u32(dsm);
    const int tid = threadIdx.x;
    const int lane = tid & 31, wid = tid >> 5;
    const int wm = wid >> 1, wn = wid & 1;
    const int gq = lane >> 2, tq = lane & 3;
    const int v0 = blockIdx.x * 128;
    const int g = lane >> 3;
    const int b_row = ((g >> 1) * 8) + (lane & 7);
    const int b_col8 = (g & 1) * 8;

    float acc[2][4][4];
    #pragma unroll
    for (int i = 0; i < 2; i++)
        #pragma unroll
        for (int j = 0; j < 4; j++)
            #pragma unroll
            for (int q = 0; q < 4; q++) acc[i][j][q] = 0.f;

    pf_out(0, 0, sbase, Wout, v0, tid); CPA_COMMIT();
    pf_out(1, 1, sbase, Wout, v0, tid); CPA_COMMIT();
    pf_out(2, 2, sbase, Wout, v0, tid); CPA_COMMIT();

    for (int c = 0; c < NCHO; c++) {
        CPA_WAIT2();
        __syncthreads();
        const int st = c & 3;
        const uint32_t wb = sbase + st * STAGE_O;
        #pragma unroll
        for (int s = 0; s < 2; s++) {
            const int kk = s * 16 + tq * 2;
            uint32_t ah[2][4], al[2][4];
            #pragma unroll
            for (int i = 0; i < 2; i++) {
                int r = wm * 32 + i * 16 + gq;
                float2 x0 = lds2(wb + swaddr(r, kk));
                float2 x1 = lds2(wb + swaddr(r + 8, kk));
                float2 x2 = lds2(wb + swaddr(r, kk + 8));
                float2 x3 = lds2(wb + swaddr(r + 8, kk + 8));
                split2t(x0.x, x0.y, ah[i][0], al[i][0]);
                split2t(x1.x, x1.y, ah[i][1], al[i][1]);
                split2t(x2.x, x2.y, ah[i][2], al[i][2]);
                split2t(x3.x, x3.y, ah[i][3], al[i][3]);
            }
            uint32_t bh2[2][4], bl2[2][4];
            #pragma unroll
            for (int j2 = 0; j2 < 2; j2++) {
                uint32_t off = (uint32_t)((wn * 32 + j2 * 16 + b_row) * 80
                                          + (s * 16 + b_col8) * 2);
                ldmx4(bh2[j2], wb + 16384 + off);
                ldmx4(bl2[j2], wb + 21504 + off);
            }
            #pragma unroll
            for (int i = 0; i < 2; i++)
                #pragma unroll
                for (int j = 0; j < 4; j++) {
                    const uint32_t* Bh = &bh2[j >> 1][(j & 1) * 2];
                    const uint32_t* Bl = &bl2[j >> 1][(j & 1) * 2];
                    mma16816(acc[i][j], ah[i], Bh);
                    mma16816(acc[i][j], ah[i], Bl);
                    mma16816(acc[i][j], al[i], Bh);
                }
        }
        pf_out(c + 3, (c + 3) & 3, sbase, Wout, v0, tid);
        CPA_COMMIT();
    }

    #pragma unroll
    for (int i = 0; i < 2; i++) {
        int v1 = v0 + wm * 32 + i * 16 + gq;
        int v2 = v1 + 8;
        float bo1 = (v1 < Vn) ? bout[v1] : 0.f;
        float bo2 = (v2 < Vn) ? bout[v2] : 0.f;
        #pragma unroll
        for (int j = 0; j < 4; j++) {
            int bb = wn * 32 + j * 8 + tq * 2;
            if (v1 < Vn) {
                pred[(size_t)bb * Vn + v1]       = acc[i][j][0] + bo1;
                pred[(size_t)(bb + 1) * Vn + v1] = acc[i][j][1] + bo1;
            }
            if (v2 < Vn) {
                pred[(size_t)bb * Vn + v2]       = acc[i][j][2] + bo2;
                pred[(size_t)(bb + 1) * Vn + v2] = acc[i][j][3] + bo2;
            }
        }
    }
}

// ---------------- launch ----------------
extern "C" void kernel_launch(void* const* d_in, const int* in_sizes, int n_in,
                              void* d_out, int out_size) {
    const int*   ids    = (const int*)  d_in[0];
    const float* hidden = (const float*)d_in[1];
    const float* enc    = (const float*)d_in[2];
    const int*   mask   = (const int*)  d_in[3];
    const float* table  = (const float*)d_in[4];
    const float* Wa     = (const float*)d_in[5];
    const float* ba     = (const float*)d_in[6];
    const float* vw     = (const float*)d_in[7];
    const float* Wih    = (const float*)d_in[8];
    const float* Whh    = (const float*)d_in[9];
    const float* bih    = (const float*)d_in[10];
    const float* bhh    = (const float*)d_in[11];
    const float* Wout   = (const float*)d_in[12];
    const float* bout   = (const float*)d_in[13];
    float* out = (float*)d_out;

    float* d_p_hid; cudaGetSymbolAddress((void**)&d_p_hid, g_p_hid);
    float* d_p_gx;  cudaGetSymbolAddress((void**)&d_p_gx,  g_p_gx);
    float* d_p_gh;  cudaGetSymbolAddress((void**)&d_p_gh,  g_p_gh);
    float* d_xin;   cudaGetSymbolAddress((void**)&d_xin,   g_xin);

    static int attr_done = 0;
    if (!attr_done) {
        cudaFuncSetAttribute(k_energy_mma, cudaFuncAttributeMaxDynamicSharedMemorySize, SMEM_E);
        cudaFuncSetAttribute(k_out_mma,    cudaFuncAttributeMaxDynamicSharedMemorySize, SMEM_O);
        attr_done = 1;
    }

    k_split_enc<<<(Sn * Bn * H2n / 4 + 255) / 256, 256>>>(enc);
    k_split_wa<<<(Hn * H2n / 4 + 255) / 256, 256>>>(Wa);
    k_emb<<<(Bn * En + 255) / 256, 256>>>(ids, table);
    k_gemm_part<<<dim3(Hn / 32, KT), 256>>>(hidden, Hn, Hn, Wa, H3n, d_p_hid, Hn);
    k_energy_mma<<<dim3(8, Bn), 256, SMEM_E>>>(vw, ba);
    k_attn_ctx<<<Bn, 256>>>(mask, enc, out);
    k_gemm_part<<<dim3(H3n / 32, KT), 256>>>(d_xin, XDIM, XDIM, Wih, XDIM, d_p_gx, H3n);
    k_gemm_part<<<dim3(H3n / 32, KT), 256>>>(hidden, Hn, Hn, Whh, Hn, d_p_gh, H3n);
    k_gru<<<(Bn * Hn + 255) / 256, 256>>>(hidden, bih, bhh, out);
    k_out_mma<<<(Vn + 127) / 128, 256, SMEM_O>>>(Wout, bout, out + PRED_OFF);
}

// round 10
// speedup vs baseline: 6.1966x; 1.0150x over previous
#include <cuda_runtime.h>
#include <cuda_bf16.h>
#include <math.h>
#include <stdint.h>

#define Bn 64
#define Sn 128
#define Hn 512
#define En 300
#define Vn 50257
#define H2n 1024
#define H3n 1536
#define XDIM 1324         // E + 2H
#define CDIM 1836         // 3H + E
#define CDIMP 1840        // padded to 16B-aligned bf16 rows
#define NEGV -1e10f
#define KT 16             // split-K factor for small GEMMs

#define PRED_OFF 0
#define HN_OFF   ((size_t)Bn * Vn)
#define A_OFF    (HN_OFF + (size_t)Bn * Hn)

// ---------------- scratch ----------------
__device__ __align__(16) float g_scorep[Bn * 8 * Sn];
__device__ __align__(16) float g_xin[Bn * XDIM];
__device__ __align__(16) float g_p_hid[KT * Bn * Hn];
__device__ __align__(16) float g_p_gx[KT * Bn * H3n];
__device__ __align__(16) float g_p_gh[KT * Bn * H3n];
__device__ __align__(16) __nv_bfloat16 g_enc_hi[(size_t)Sn * Bn * H2n];
__device__ __align__(16) __nv_bfloat16 g_enc_lo[(size_t)Sn * Bn * H2n];
__device__ __align__(16) __nv_bfloat16 g_wa_hi[Hn * H2n];
__device__ __align__(16) __nv_bfloat16 g_wa_lo[Hn * H2n];
__device__ __align__(16) __nv_bfloat16 g_xcat_hi[Bn * CDIMP];
__device__ __align__(16) __nv_bfloat16 g_xcat_lo[Bn * CDIMP];

// ---------------- helpers ----------------
__device__ __forceinline__ uint32_t smem_u32(const void* p) {
    uint32_t a;
    asm("{ .reg .u64 t; cvta.to.shared.u64 t, %1; cvt.u32.u64 %0, t; }" : "=r"(a) : "l"(p));
    return a;
}
__device__ __forceinline__ float2 lds2(uint32_t a) {
    float2 v;
    asm volatile("ld.shared.v2.f32 {%0,%1}, [%2];" : "=f"(v.x), "=f"(v.y) : "r"(a));
    return v;
}
__device__ __forceinline__ void cpa_cg(uint32_t dst, const void* src, int bytes) {
    asm volatile("cp.async.cg.shared.global [%0], [%1], 16, %2;"
                 :: "r"(dst), "l"(src), "r"(bytes) : "memory");
}
#define CPA_COMMIT() asm volatile("cp.async.commit_group;" ::: "memory")
#define CPA_WAIT1()  asm volatile("cp.async.wait_group 1;" ::: "memory")
#define CPA_WAIT2()  asm volatile("cp.async.wait_group 2;" ::: "memory")

__device__ __forceinline__ void ldmx4(uint32_t* r, uint32_t addr) {
    asm volatile("ldmatrix.sync.aligned.m8n8.x4.shared.b16 {%0,%1,%2,%3}, [%4];"
                 : "=r"(r[0]), "=r"(r[1]), "=r"(r[2]), "=r"(r[3]) : "r"(addr));
}
__device__ __forceinline__ void mma16816(float* c, const uint32_t* a, const uint32_t* b) {
    asm volatile("mma.sync.aligned.m16n8k16.row.col.f32.bf16.bf16.f32 "
                 "{%0,%1,%2,%3}, {%4,%5,%6,%7}, {%8,%9}, {%0,%1,%2,%3};"
                 : "+f"(c[0]), "+f"(c[1]), "+f"(c[2]), "+f"(c[3])
                 : "r"(a[0]), "r"(a[1]), "r"(a[2]), "r"(a[3]), "r"(b[0]), "r"(b[1]));
}
__device__ __forceinline__ void split2t(float x, float y, uint32_t& hiw, uint32_t& low) {
    uint32_t xb = __float_as_uint(x), yb = __float_as_uint(y);
    uint32_t hx = xb & 0xFFFF0000u, hy = yb & 0xFFFF0000u;
    hiw = (hx >> 16) | hy;
    float lx = x - __uint_as_float(hx);
    float ly = y - __uint_as_float(hy);
    asm("cvt.rn.bf16x2.f32 %0, %1, %2;" : "=r"(low) : "f"(ly), "f"(lx));
}
__device__ __forceinline__ uint32_t swaddr(int row, int k) {
    return (uint32_t)(row * 128 + ((((k >> 2) ^ (row & 7)) << 4)) + (k & 3) * 4);
}
__device__ __forceinline__ void split_store(float val, int idx) {
    uint32_t xb = __float_as_uint(val) & 0xFFFF0000u;
    unsigned short ht = (unsigned short)(xb >> 16);
    g_xcat_hi[idx] = *reinterpret_cast<__nv_bfloat16*>(&ht);
    g_xcat_lo[idx] = __float2bfloat16_rn(val - __uint_as_float(xb));
}

// ---------------- split-K partial GEMM body ----------------
__device__ __forceinline__ void gemm_part_body(
        const float* __restrict__ A, int astride, int K,
        const float* __restrict__ W, int wstride,
        float* __restrict__ outp, int ostride, int j0, int ky) {
    __shared__ float As[32][65];
    __shared__ float Ws[32][33];
    const int ksl = (((K + KT - 1) / KT) + 31) & ~31;
    const int kb = ky * ksl;
    const int ke = (K < kb + ksl) ? K : (kb + ksl);
    float* op = outp + (size_t)ky * Bn * ostride;
    const int tid = threadIdx.x;
    const int tx = tid & 7, ty = tid >> 3;   // tx: 4 j, ty: 2 b
    float acc[2][4];
    #pragma unroll
    for (int i = 0; i < 2; i++)
        #pragma unroll
        for (int j = 0; j < 4; j++) acc[i][j] = 0.f;

    for (int k0 = kb; k0 < ke; k0 += 32) {
        #pragma unroll
        for (int it = 0; it < 8; it++) {
            int idx = tid + it * 256;
            int b = idx >> 5, k = idx & 31;
            As[k][b] = (k0 + k < ke) ? A[(size_t)b * astride + k0 + k] : 0.f;
        }
        #pragma unroll
        for (int it = 0; it < 4; it++) {
            int idx = tid + it * 256;
            int j = idx >> 5, k = idx & 31;
            Ws[k][j] = (k0 + k < ke) ? W[(size_t)(j0 + j) * wstride + k0 + k] : 0.f;
        }
        __syncthreads();
        #pragma unroll
        for (int kk = 0; kk < 32; kk++) {
            float a0 = As[kk][ty * 2], a1 = As[kk][ty * 2 + 1];
            float w[4];
            #pragma unroll
            for (int j = 0; j < 4; j++) w[j] = Ws[kk][tx * 4 + j];
            #pragma unroll
            for (int j = 0; j < 4; j++) {
                acc[0][j] += a0 * w[j];
                acc[1][j] += a1 * w[j];
            }
        }
        __syncthreads();
    }
    #pragma unroll
    for (int i = 0; i < 2; i++) {
        int b = ty * 2 + i;
        #pragma unroll
        for (int j = 0; j < 4; j++)
            op[(size_t)b * ostride + j0 + tx * 4 + j] = acc[i][j];
    }
}

// ---------------- 1) prep mega-kernel: split_enc | split_wa | gemm_hid | gemm_gh ----------------
#define NB_SE 8192
#define NB_WA 512
#define NB_HID (16 * KT)    // 16 j-tiles x KT
#define NB_GH  (48 * KT)    // 48 j-tiles x KT
#define NB_PREP (NB_SE + NB_WA + NB_HID + NB_GH)

__global__ __launch_bounds__(256)
void k_prep(const float* __restrict__ enc, const float* __restrict__ Wa,
            const float* __restrict__ hidden, const float* __restrict__ Whh) {
    const int bid = blockIdx.x;
    const int tid = threadIdx.x;
    if (bid < NB_SE) {
        size_t i4 = (size_t)bid * 256 + tid;
        float4 v = ((const float4*)enc)[i4];
        uint32_t h01, l01, h23, l23;
        split2t(v.x, v.y, h01, l01);
        split2t(v.z, v.w, h23, l23);
        ((uint32_t*)g_enc_hi)[i4 * 2]     = h01;
        ((uint32_t*)g_enc_hi)[i4 * 2 + 1] = h23;
        ((uint32_t*)g_enc_lo)[i4 * 2]     = l01;
        ((uint32_t*)g_enc_lo)[i4 * 2 + 1] = l23;
    } else if (bid < NB_SE + NB_WA) {
        int i4 = (bid - NB_SE) * 256 + tid;
        int h = i4 >> 8, k4 = i4 & 255;
        const float4 v = *(const float4*)(Wa + (size_t)h * H3n + Hn + k4 * 4);
        uint32_t h01, l01, h23, l23;
        split2t(v.x, v.y, h01, l01);
        split2t(v.z, v.w, h23, l23);
        int d = h * 512 + k4 * 2;
        ((uint32_t*)g_wa_hi)[d]     = h01;
        ((uint32_t*)g_wa_hi)[d + 1] = h23;
        ((uint32_t*)g_wa_lo)[d]     = l01;
        ((uint32_t*)g_wa_lo)[d + 1] = l23;
    } else if (bid < NB_SE + NB_WA + NB_HID) {
        int q = bid - NB_SE - NB_WA;
        gemm_part_body(hidden, Hn, Hn, Wa, H3n, g_p_hid, Hn,
                       (q & 15) * 32, q >> 4);
    } else {
        int q = bid - NB_SE - NB_WA - NB_HID;
        gemm_part_body(hidden, Hn, Hn, Whh, Hn, g_p_gh, H3n,
                       (q % 48) * 32, q / 48);
    }
}

// ---------------- 2) energy GEMM: ldmatrix+HMMA, 3-stage ----------------
#define NCHE 32
#define STAGE_E 30720
#define SMEM_E  (3 * STAGE_E)

__device__ __forceinline__ void pf_energy(int c, int st, uint32_t sbase,
                                          int b, int h0, int tid) {
    if (c >= NCHE) return;
    int k0 = c * 32;
    uint32_t ab = sbase + st * STAGE_E;
    #pragma unroll
    for (int pl = 0; pl < 2; pl++) {
        const __nv_bfloat16* srcA = pl ? g_enc_lo : g_enc_hi;
        #pragma unroll
        for (int it = 0; it < 2; it++) {
            int idx = tid + it * 256;
            int row = idx >> 2, ch = idx & 3;
            cpa_cg(ab + pl * 10240 + row * 80 + ch * 16,
                   srcA + ((size_t)(row * Bn + b)) * H2n + k0 + ch * 8, 16);
        }
        const __nv_bfloat16* srcB = pl ? g_wa_lo : g_wa_hi;
        {
            int row = tid >> 2, ch = tid & 3;
            cpa_cg(ab + 20480 + pl * 5120 + row * 80 + ch * 16,
                   srcB + (size_t)(h0 + row) * H2n + k0 + ch * 8, 16);
        }
    }
}

__global__ __launch_bounds__(256, 2)
void k_energy_mma(const float* __restrict__ vw, const float* __restrict__ ba) {
    extern __shared__ __align__(16) char dsm[];
    const uint32_t sbase = smem_u32(dsm);
    __shared__ float s_hid[64];
    __shared__ float s_vw[64];
    __shared__ float s_red[128][2];

    const int tid = threadIdx.x;
    const int lane = tid & 31, wid = tid >> 5;
    const int wm = wid >> 1, wn = wid & 1;
    const int gq = lane >> 2, tq = lane & 3;
    const int hc = blockIdx.x, b = blockIdx.y;
    const int h0 = hc * 64;

    if (tid < 64) {
        float v = ba[h0 + tid];
        #pragma unroll
        for (int cc = 0; cc < KT; cc++)
            v += g_p_hid[((size_t)cc * Bn + b) * Hn + h0 + tid];
        s_hid[tid] = v;
        s_vw[tid]  = vw[h0 + tid];
    }

    const int a_row = lane & 15;
    const int a_col8 = (lane >> 4) * 8;
    const int g = lane >> 3;
    const int b_row = ((g >> 1) * 8) + (lane & 7);
    const int b_col8 = (g & 1) * 8;

    float acc[2][4][4];
    #pragma unroll
    for (int i = 0; i < 2; i++)
        #pragma unroll
        for (int j = 0; j < 4; j++)
            #pragma unroll
            for (int q = 0; q < 4; q++) acc[i][j][q] = 0.f;

    pf_energy(0, 0, sbase, b, h0, tid); CPA_COMMIT();
    pf_energy(1, 1, sbase, b, h0, tid); CPA_COMMIT();

    for (int c = 0; c < NCHE; c++) {
        CPA_WAIT1();
        __syncthreads();
        const int st = c % 3;
        const uint32_t ab = sbase + st * STAGE_E;
        #pragma unroll
        for (int s = 0; s < 2; s++) {
            uint32_t ah[2][4], al[2][4];
            #pragma unroll
            for (int i = 0; i < 2; i++) {
                uint32_t off = (uint32_t)((wm * 32 + i * 16 + a_row) * 80
                                          + (s * 16 + a_col8) * 2);
                ldmx4(ah[i], ab + off);
                ldmx4(al[i], ab + 10240 + off);
            }
            uint32_t bh2[2][4], bl2[2][4];
            #pragma unroll
            for (int j2 = 0; j2 < 2; j2++) {
                uint32_t off = (uint32_t)((wn * 32 + j2 * 16 + b_row) * 80
                                          + (s * 16 + b_col8) * 2);
                ldmx4(bh2[j2], ab + 20480 + off);
                ldmx4(bl2[j2], ab + 25600 + off);
            }
            #pragma unroll
            for (int i = 0; i < 2; i++)
                #pragma unroll
                for (int j = 0; j < 4; j++) {
                    const uint32_t* Bh = &bh2[j >> 1][(j & 1) * 2];
                    const uint32_t* Bl = &bl2[j >> 1][(j & 1) * 2];
                    mma16816(acc[i][j], ah[i], Bh);
                    mma16816(acc[i][j], ah[i], Bl);
                    mma16816(acc[i][j], al[i], Bh);
                }
        }
        pf_energy(c + 2, (c + 2) % 3, sbase, b, h0, tid);
        CPA_COMMIT();
    }

    #pragma unroll
    for (int i = 0; i < 2; i++) {
        float p1 = 0.f, p2 = 0.f;
        #pragma unroll
        for (int j = 0; j < 4; j++) {
            int hl = wn * 32 + j * 8 + tq * 2;
            float v0 = s_vw[hl], v1 = s_vw[hl + 1];
            float hp0 = s_hid[hl], hp1 = s_hid[hl + 1];
            p1 += v0 * tanhf(acc[i][j][0] + hp0) + v1 * tanhf(acc[i][j][1] + hp1);
            p2 += v0 * tanhf(acc[i][j][2] + hp0) + v1 * tanhf(acc[i][j][3] + hp1);
        }
        p1 += __shfl_xor_sync(0xffffffffu, p1, 1);
        p1 += __shfl_xor_sync(0xffffffffu, p1, 2);
        p2 += __shfl_xor_sync(0xffffffffu, p2, 1);
        p2 += __shfl_xor_sync(0xffffffffu, p2, 2);
        if (tq == 0) {
            int s1 = wm * 32 + i * 16 + gq;
            s_red[s1][wn] = p1;
            s_red[s1 + 8][wn] = p2;
        }
    }
    __syncthreads();
    if (tid < 128)
        g_scorep[(b * 8 + hc) * Sn + tid] = s_red[tid][0] + s_red[tid][1];
}

// ---------------- 3) fused emb + softmax + weighted + xin + xcat ----------------
__global__ __launch_bounds__(256)
void k_attn_ctx(const int* __restrict__ ids, const float* __restrict__ table,
                const int* __restrict__ mask, const float* __restrict__ enc,
                float* __restrict__ out_a) {
    const int b = blockIdx.x;
    const int tid = threadIdx.x;
    __shared__ float red[128];
    __shared__ float a_s[Sn];

    float v = 0.f;
    if (tid < 128) {
        #pragma unroll
        for (int c = 0; c < 8; c++) v += g_scorep[(b * 8 + c) * Sn + tid];
        if (mask[b * Sn + tid] == 0) v = NEGV;
        red[tid] = v;
    }
    __syncthreads();
    #pragma unroll
    for (int off = 64; off > 0; off >>= 1) {
        if (tid < off) red[tid] = fmaxf(red[tid], red[tid + off]);
        __syncthreads();
    }
    float m = red[0];
    __syncthreads();
    float e = 0.f;
    if (tid < 128) { e = expf(v - m); red[tid] = e; }
    __syncthreads();
    #pragma unroll
    for (int off = 64; off > 0; off >>= 1) {
        if (tid < off) red[tid] += red[tid + off];
        __syncthreads();
    }
    if (tid < 128) {
        float a = e / red[0];
        a_s[tid] = a;
        out_a[A_OFF + b * Sn + tid] = a;
    }
    __syncthreads();

    // weighted[b, e0..e0+3]
    const int e0 = tid * 4;
    float4 acc = make_float4(0.f, 0.f, 0.f, 0.f);
    #pragma unroll 4
    for (int s = 0; s < Sn; s++) {
        float a = a_s[s];
        float4 ev = *(const float4*)(enc + ((size_t)(s * Bn + b)) * H2n + e0);
        acc.x += a * ev.x; acc.y += a * ev.y; acc.z += a * ev.z; acc.w += a * ev.w;
    }
    *(float4*)(g_xin + (size_t)b * XDIM + En + e0) = acc;
    int cb = b * CDIMP + Hn + e0;
    split_store(acc.x, cb);
    split_store(acc.y, cb + 1);
    split_store(acc.z, cb + 2);
    split_store(acc.w, cb + 3);

    // embedding gather into xin and xcat
    const int id = ids[b];
    for (int idx = tid; idx < En; idx += 256) {
        float val = table[(size_t)id * En + idx];
        g_xin[(size_t)b * XDIM + idx] = val;
        split_store(val, b * CDIMP + Hn + H2n + idx);
    }
    // pad
    if (tid < CDIMP - CDIM) {
        g_xcat_hi[b * CDIMP + CDIM + tid] = __float2bfloat16_rn(0.f);
        g_xcat_lo[b * CDIMP + CDIM + tid] = __float2bfloat16_rn(0.f);
    }
}

// ---------------- 4) gx partial GEMM ----------------
__global__ __launch_bounds__(256)
void k_gemm_gx(const float* __restrict__ Wih) {
    gemm_part_body(g_xin, XDIM, XDIM, Wih, XDIM, g_p_gx, H3n,
                   blockIdx.x * 32, blockIdx.y);
}

// ---------------- 5) gates + h_new + xcat(h_new) ----------------
__global__ void k_gru(const float* __restrict__ hidden,
                      const float* __restrict__ bih, const float* __restrict__ bhh,
                      float* __restrict__ out) {
    int idx = blockIdx.x * blockDim.x + threadIdx.x;
    if (idx >= Bn * Hn) return;
    int b = idx / Hn, c = idx - b * Hn;
    float gx0 = bih[c], gx1 = bih[Hn + c], gx2 = bih[2 * Hn + c];
    float gh0 = bhh[c], gh1 = bhh[Hn + c], gh2 = bhh[2 * Hn + c];
    #pragma unroll
    for (int cc = 0; cc < KT; cc++) {
        size_t base = ((size_t)cc * Bn + b) * H3n;
        gx0 += g_p_gx[base + c];
        gx1 += g_p_gx[base + Hn + c];
        gx2 += g_p_gx[base + 2 * Hn + c];
        gh0 += g_p_gh[base + c];
        gh1 += g_p_gh[base + Hn + c];
        gh2 += g_p_gh[base + 2 * Hn + c];
    }
    float r = 1.f / (1.f + expf(-(gx0 + gh0)));
    float z = 1.f / (1.f + expf(-(gx1 + gh1)));
    float n = tanhf(gx2 + r * gh2);
    float val = (1.f - z) * n + z * hidden[(size_t)b * Hn + c];
    out[HN_OFF + b * Hn + c] = val;
    split_store(val, b * CDIMP + c);
}

// ---------------- 6) output GEMM: 4-stage pipeline ----------------
#define NCHO 58
#define STAGE_O 26624      // W fp32 16384 | Xhi 5120 | Xlo 5120
#define SMEM_O  (4 * STAGE_O)

__device__ __forceinline__ void pf_out(int c, int st, uint32_t sbase,
                                       const float* Wout, int v0, int tid) {
    if (c >= NCHO) return;
    int k0 = c * 32;
    uint32_t wb = sbase + st * STAGE_O;
    #pragma unroll
    for (int it = 0; it < 4; it++) {
        int m = tid + it * 256;
        int row = m >> 3, kc = m & 7;
        int vr = v0 + row; if (vr >= Vn) vr = Vn - 1;
        int gk = k0 + kc * 4;
        int rem = CDIM - gk;
        int bytes = rem >= 4 ? 16 : (rem > 0 ? rem * 4 : 0);
        int gko = rem > 0 ? gk : 0;
        cpa_cg(wb + row * 128 + (((kc ^ (row & 7)) << 4)),
               Wout + (size_t)vr * CDIM + gko, bytes);
    }
    #pragma unroll
    for (int pl = 0; pl < 2; pl++) {
        const __nv_bfloat16* src = pl ? g_xcat_lo : g_xcat_hi;
        int row = tid >> 2, ch = tid & 3;
        int gk = k0 + ch * 8;
        int rem = CDIMP - gk;
        int bytes = rem >= 8 ? 16 : (rem > 0 ? rem * 2 : 0);
        int gko = rem > 0 ? gk : 0;
        cpa_cg(wb + 16384 + pl * 5120 + row * 80 + ch * 16,
               src + (size_t)row * CDIMP + gko, bytes);
    }
}

__global__ __launch_bounds__(256, 2)
void k_out_mma(const float* __restrict__ Wout, const float* __restrict__ bout,
               float* __restrict__ pred) {
    extern __shared__ __align__(16) char dsm[];
    const uint32_t sbase = smem_u32(dsm);
    const int tid = threadIdx.x;
    const int lane = tid & 31, wid = tid >> 5;
    const int wm = wid >> 1, wn = wid & 1;
    const int gq = lane >> 2, tq = lane & 3;
    const int v0 = blockIdx.x * 128;
    const int g = lane >> 3;
    const int b_row = ((g >> 1) * 8) + (lane & 7);
    const int b_col8 = (g & 1) * 8;

    float acc[2][4][4];
    #pragma unroll
    for (int i = 0; i < 2; i++)
        #pragma unroll
        for (int j = 0; j < 4; j++)
            #pragma unroll
            for (int q = 0; q < 4; q++) acc[i][j][q] = 0.f;

    pf_out(0, 0, sbase, Wout, v0, tid); CPA_COMMIT();
    pf_out(1, 1, sbase, Wout, v0, tid); CPA_COMMIT();
    pf_out(2, 2, sbase, Wout, v0, tid); CPA_COMMIT();

    for (int c = 0; c < NCHO; c++) {
        CPA_WAIT2();
        __syncthreads();
        const int st = c & 3;
        const uint32_t wb = sbase + st * STAGE_O;
        #pragma unroll
        for (int s = 0; s < 2; s++) {
            const int kk = s * 16 + tq * 2;
            uint32_t ah[2][4], al[2][4];
            #pragma unroll
            for (int i = 0; i < 2; i++) {
                int r = wm * 32 + i * 16 + gq;
                float2 x0 = lds2(wb + swaddr(r, kk));
                float2 x1 = lds2(wb + swaddr(r + 8, kk));
                float2 x2 = lds2(wb + swaddr(r, kk + 8));
                float2 x3 = lds2(wb + swaddr(r + 8, kk + 8));
                split2t(x0.x, x0.y, ah[i][0], al[i][0]);
                split2t(x1.x, x1.y, ah[i][1], al[i][1]);
                split2t(x2.x, x2.y, ah[i][2], al[i][2]);
                split2t(x3.x, x3.y, ah[i][3], al[i][3]);
            }
            uint32_t bh2[2][4], bl2[2][4];
            #pragma unroll
            for (int j2 = 0; j2 < 2; j2++) {
                uint32_t off = (uint32_t)((wn * 32 + j2 * 16 + b_row) * 80
                                          + (s * 16 + b_col8) * 2);
                ldmx4(bh2[j2], wb + 16384 + off);
                ldmx4(bl2[j2], wb + 21504 + off);
            }
            #pragma unroll
            for (int i = 0; i < 2; i++)
                #pragma unroll
                for (int j = 0; j < 4; j++) {
                    const uint32_t* Bh = &bh2[j >> 1][(j & 1) * 2];
                    const uint32_t* Bl = &bl2[j >> 1][(j & 1) * 2];
                    mma16816(acc[i][j], ah[i], Bh);
                    mma16816(acc[i][j], ah[i], Bl);
                    mma16816(acc[i][j], al[i], Bh);
                }
        }
        pf_out(c + 3, (c + 3) & 3, sbase, Wout, v0, tid);
        CPA_COMMIT();
    }

    #pragma unroll
    for (int i = 0; i < 2; i++) {
        int v1 = v0 + wm * 32 + i * 16 + gq;
        int v2 = v1 + 8;
        float bo1 = (v1 < Vn) ? bout[v1] : 0.f;
        float bo2 = (v2 < Vn) ? bout[v2] : 0.f;
        #pragma unroll
        for (int j = 0; j < 4; j++) {
            int bb = wn * 32 + j * 8 + tq * 2;
            if (v1 < Vn) {
                pred[(size_t)bb * Vn + v1]       = acc[i][j][0] + bo1;
                pred[(size_t)(bb + 1) * Vn + v1] = acc[i][j][1] + bo1;
            }
            if (v2 < Vn) {
                pred[(size_t)bb * Vn + v2]       = acc[i][j][2] + bo2;
                pred[(size_t)(bb + 1) * Vn + v2] = acc[i][j][3] + bo2;
            }
        }
    }
}

// ---------------- launch ----------------
extern "C" void kernel_launch(void* const* d_in, const int* in_sizes, int n_in,
                              void* d_out, int out_size) {
    const int*   ids    = (const int*)  d_in[0];
    const float* hidden = (const float*)d_in[1];
    const float* enc    = (const float*)d_in[2];
    const int*   mask   = (const int*)  d_in[3];
    const float* table  = (const float*)d_in[4];
    const float* Wa     = (const float*)d_in[5];
    const float* ba     = (const float*)d_in[6];
    const float* vw     = (const float*)d_in[7];
    const float* Wih    = (const float*)d_in[8];
    const float* Whh    = (const float*)d_in[9];
    const float* bih    = (const float*)d_in[10];
    const float* bhh    = (const float*)d_in[11];
    const float* Wout   = (const float*)d_in[12];
    const float* bout   = (const float*)d_in[13];
    float* out = (float*)d_out;

    static int attr_done = 0;
    if (!attr_done) {
        cudaFuncSetAttribute(k_energy_mma, cudaFuncAttributeMaxDynamicSharedMemorySize, SMEM_E);
        cudaFuncSetAttribute(k_out_mma,    cudaFuncAttributeMaxDynamicSharedMemorySize, SMEM_O);
        attr_done = 1;
    }

    k_prep<<<NB_PREP, 256>>>(enc, Wa, hidden, Whh);
    k_energy_mma<<<dim3(8, Bn), 256, SMEM_E>>>(vw, ba);
    k_attn_ctx<<<Bn, 256>>>(ids, table, mask, enc, out);
    k_gemm_gx<<<dim3(48, KT), 256>>>(Wih);
    k_gru<<<(Bn * Hn + 255) / 256, 256>>>(hidden, bih, bhh, out);
    k_out_mma<<<(Vn + 127) / 128, 256, SMEM_O>>>(Wout, bout, out + PRED_OFF);
}